// round 13
// baseline (speedup 1.0000x reference)
#include <cuda_runtime.h>
#include <cuda_bf16.h>

#define MESH 8
#define NN   512
#define NEx  409
#define NIx  103
#define DD   243
#define BB   512
// K layout: [0,448) own E, [448,576) own I (weights x8192), [576,1024) prev-mesh E.
// Stage-major storage, 16 stages of 64 k (128B swizzled rows).
#define KT      1024
#define K_ISEC  448
#define K_PSEC  576
#define ISCALE  8192.0f
#define NS      16
#define OWN_STG 9
#define NTHR    256       // 8 warps; 2 CTAs per SM
#define SLOT_A  16384u
#define SLOT_B  8192u
#define SLOTSZ  24576u
#define VSTR    72

// ---------------- device state (stage-major, SW128-swizzled 128B rows) ----------------
__device__ __align__(16) __nv_bfloat16 g_Wbig[MESH][NS][NN][64];
__device__ __align__(16) __nv_bfloat16 g_Abuf[2][MESH][NS][BB][64];
__device__ float g_WinT[MESH][DD][NN];
__device__ float g_ext[MESH][BB][NN];
__device__ float4 g_extp[MESH][4][8][8][256];   // [m][bt][nt][q][tid] thread-owned ext
__device__ unsigned g_bar;

__device__ __forceinline__ float quantw(float w) {
    float q = rintf(w);                  // round-half-even == jnp.round
    return fminf(7.f, fmaxf(-8.f, q));
}

// ---------------- combined init (zero + Wbig + WinT) ----------------
__global__ void k_init(const float* __restrict__ W_in, const float* __restrict__ W_inter,
                       const float* __restrict__ W_EE, const float* __restrict__ W_EI,
                       const float* __restrict__ W_IE, const float* __restrict__ W_II) {
    long long stride = (long long)gridDim.x * blockDim.x;
    long long i0 = (long long)blockIdx.x * blockDim.x + threadIdx.x;
    if (i0 == 0) g_bar = 0u;

    unsigned* A = (unsigned*)&g_Abuf[0][0][0][0][0];
    long long nA = 2LL * MESH * BB * KT / 2;
    for (long long i = i0; i < nA; i += stride) A[i] = 0u;

    long long totW = (long long)MESH * NN * KT;
    for (long long idx = i0; idx < totW; idx += stride) {
        int k = (int)(idx % KT);
        int n = (int)((idx / KT) % NN);
        int m = (int)(idx / ((long long)KT * NN));
        float w = 0.f;
        if (k < K_ISEC) {                        // E-driven: W_EE / W_EI
            if (k < NEx)
                w = (n < NEx) ? W_EE[((long long)m * NEx + n) * NEx + k]
                              : W_EI[((long long)m * NIx + (n - NEx)) * NEx + k];
            w = quantw(w);
        } else if (k < K_PSEC) {                 // I-driven, packed *8192 (exact in bf16)
            int ki = k - K_ISEC;
            if (ki < NIx)
                w = (n < NEx) ? W_IE[((long long)m * NEx + n) * NIx + ki]
                              : W_II[((long long)m * NIx + (n - NEx)) * NIx + ki];
            w = quantw(w) * ISCALE;
        } else {                                 // inter: mesh m receives W_inter[m-1]
            int kp = k - K_PSEC;
            if (kp < NEx) {
                int mp = (m + MESH - 1) % MESH;
                w = W_inter[((long long)mp * NN + n) * NEx + kp];
            }
            w = quantw(w);
        }
        int st = k >> 6, kk = k & 63;
        unsigned off = ((unsigned)(2 * kk)) ^ (((unsigned)n & 7u) << 4);   // SW128 within row
        *(__nv_bfloat16*)((char*)&g_Wbig[m][st][n][0] + off) = __float2bfloat16(w);
    }

    long long totI = (long long)MESH * NN * DD;
    for (long long idx = i0; idx < totI; idx += stride) {
        int d = (int)(idx % DD);
        int n = (int)((idx / DD) % NN);
        int m = (int)(idx / ((long long)DD * NN));
        g_WinT[m][d][n] = quantw(W_in[idx]);
    }
}

// ---------------- ext_proj: f32x2 packed serial-d FMA (per-half bitwise == scalar) ------
#define EXT_BT 16
__device__ __forceinline__ unsigned long long fma2(unsigned long long a, unsigned long long b,
                                                   unsigned long long c) {
    unsigned long long d;
    asm("fma.rn.f32x2 %0, %1, %2, %3;" : "=l"(d) : "l"(a), "l"(b), "l"(c));
    return d;
}
__global__ void __launch_bounds__(512)
k_ext(const float* __restrict__ X, const float* __restrict__ b_in) {
    __shared__ __align__(16) float sx[DD][EXT_BT];
    const int m  = blockIdx.y;
    const int b0 = blockIdx.x * EXT_BT;
    const int n  = threadIdx.x;
    for (int i = threadIdx.x; i < EXT_BT * DD; i += 512) {
        int bb = i / DD, d = i % DD;
        sx[d][bb] = X[(long long)(b0 + bb) * DD + d];
    }
    __syncthreads();
    unsigned long long acc2[8];
    #pragma unroll
    for (int q = 0; q < 8; ++q) acc2[q] = 0ull;
    for (int d = 0; d < DD; ++d) {
        float w = g_WinT[m][d][n];
        unsigned long long w2;
        asm("mov.b64 %0, {%1,%1};" : "=l"(w2) : "r"(__float_as_uint(w)));
        const unsigned long long* p = reinterpret_cast<const unsigned long long*>(&sx[d][0]);
        #pragma unroll
        for (int q = 0; q < 8; ++q) acc2[q] = fma2(p[q], w2, acc2[q]);
    }
    float bi = b_in[m * NN + n];
    #pragma unroll
    for (int q = 0; q < 8; ++q) {
        unsigned lo, hi;
        asm("mov.b64 {%0,%1}, %2;" : "=r"(lo), "=r"(hi) : "l"(acc2[q]));
        g_ext[m][b0 + 2 * q][n]     = __fadd_rn(__uint_as_float(lo), bi);
        g_ext[m][b0 + 2 * q + 1][n] = __fadd_rn(__uint_as_float(hi), bi);
    }
}

// ---------------- permute ext into thread-owned float4 layout ----------------
__global__ void k_perm() {
    long long stride = (long long)gridDim.x * blockDim.x;
    long long tot = (long long)MESH * 4 * 8 * 8 * 256;
    for (long long g = (long long)blockIdx.x * blockDim.x + threadIdx.x; g < tot; g += stride) {
        int tid = (int)(g & 255);
        int q   = (int)((g >> 8) & 7);
        int nt  = (int)((g >> 11) & 7);
        int bt  = (int)((g >> 14) & 3);
        int m   = (int)(g >> 16);
        int im = q >> 2, in = q & 3;
        int warp = tid >> 5, lane = tid & 31;
        int wm = warp >> 1, wn = warp & 1;
        float4 v4;
        float* vp = &v4.x;
        #pragma unroll
        for (int f = 0; f < 4; ++f) {
            int r = wm * 32 + im * 16 + (lane >> 2) + (f >> 1) * 8;
            int c = wn * 32 + in * 8 + (lane & 3) * 2 + (f & 1);
            vp[f] = g_ext[m][bt * 128 + r][nt * 64 + c];
        }
        g_extp[m][bt][nt][q][tid] = v4;
    }
}

// ---------------- asm helpers ----------------
__device__ __forceinline__ void ldm4(unsigned* r, unsigned addr) {
    asm volatile("ldmatrix.sync.aligned.m8n8.x4.shared.b16 {%0,%1,%2,%3}, [%4];\n"
                 : "=r"(r[0]), "=r"(r[1]), "=r"(r[2]), "=r"(r[3]) : "r"(addr));
}
__device__ __forceinline__ void mma16816(float* c, const unsigned* a, unsigned b0, unsigned b1) {
    asm volatile("mma.sync.aligned.m16n8k16.row.col.f32.bf16.bf16.f32 "
                 "{%0,%1,%2,%3}, {%4,%5,%6,%7}, {%8,%9}, {%0,%1,%2,%3};\n"
                 : "+f"(c[0]), "+f"(c[1]), "+f"(c[2]), "+f"(c[3])
                 : "r"(a[0]), "r"(a[1]), "r"(a[2]), "r"(a[3]), "r"(b0), "r"(b1));
}
__device__ __forceinline__ void bulk_ld(unsigned dst, const void* src, unsigned bytes,
                                        unsigned mbar) {
    asm volatile("cp.async.bulk.shared::cluster.global.mbarrier::complete_tx::bytes "
                 "[%0], [%1], %2, [%3];"
                 :: "r"(dst), "l"(src), "r"(bytes), "r"(mbar) : "memory");
}
__device__ __forceinline__ void mbar_expect(unsigned mbar, unsigned bytes) {
    asm volatile("mbarrier.arrive.expect_tx.shared.b64 _, [%0], %1;"
                 :: "r"(mbar), "r"(bytes) : "memory");
}
__device__ __forceinline__ void mbar_arrive(unsigned mbar) {
    asm volatile("mbarrier.arrive.shared.b64 _, [%0];" :: "r"(mbar) : "memory");
}
__device__ __forceinline__ void mbar_wait(unsigned addr, unsigned parity) {
    unsigned done;
    do {
        asm volatile(
            "{\n\t.reg .pred p;\n\t"
            "mbarrier.try_wait.parity.shared.b64 p, [%1], %2, 0x989680;\n\t"
            "selp.b32 %0, 1, 0, p;\n\t}"
            : "=r"(done) : "r"(addr), "r"(parity) : "memory");
    } while (!done);
}

__device__ __forceinline__ void grid_barrier(unsigned phase) {
    __threadfence();
    __syncthreads();
    if (threadIdx.x == 0) {
        asm volatile("red.release.gpu.global.add.u32 [%0], %1;" :: "l"(&g_bar), "r"(1u) : "memory");
        unsigned target = phase * 256u, v;
        do {
            asm volatile("ld.acquire.gpu.global.u32 %0, [%1];" : "=r"(v) : "l"(&g_bar) : "memory");
            if (v < target) __nanosleep(64);
        } while (v < target);
    }
    __syncthreads();
}

// scattered spike write (stage-major + SW128 swizzle)
__device__ __forceinline__ void write_spike(int wbuf, int m, int grow, int gc, bool sp) {
    unsigned short h = sp ? 0x3F80 : 0;
    unsigned sw = (((unsigned)grow & 7u) << 4);
    int kown = (gc < NEx) ? gc : (gc + (K_ISEC - NEx));
    int st = kown >> 6, kk = kown & 63;
    *(unsigned short*)((char*)&g_Abuf[wbuf][m][st][grow][0] + (((unsigned)(2 * kk)) ^ sw)) = h;
    if (gc < NEx) {
        int kp = K_PSEC + gc;
        *(unsigned short*)((char*)&g_Abuf[wbuf][(m + 1) & 7][kp >> 6][grow][0]
                           + (((unsigned)(2 * (kp & 63))) ^ sw)) = h;
    }
}

// ---------------- persistent bf16-HMMA reservoir (2 CTAs/SM, tile 128x64) -------------
// smem: ring 3 x (A 16K @+0, B 8K @+16K) = 72K | v f32 stride 72 (36.9K) | mbars
#define SMO_V    73728
#define SMO_MBAR 110592
#define SM_DYN   110720

__global__ void __launch_bounds__(NTHR, 2)
k_persist(float* __restrict__ dout, float decayI) {
    extern __shared__ __align__(16) char sm[];
    float* sv = (float*)(sm + SMO_V);    // [r*72 + c], 128 x 64

    const int m   = blockIdx.z;
    const int bt  = blockIdx.y;
    const int nt  = blockIdx.x;
    const int bm0 = bt * 128;
    const int bn0 = nt * 64;
    const int tid  = threadIdx.x;
    const int lane = tid & 31, warp = tid >> 5;
    const int wm = warp >> 1, wn = warp & 1;      // 4x2 warps, warp tile 32x32

    unsigned smb   = (unsigned)__cvta_generic_to_shared(sm);
    unsigned mbarb = smb + SMO_MBAR;              // full: +0,8,16 ; empty: +24,32,40

    const float4* xp = &g_extp[m][bt][nt][0][tid];   // xp[q*256]

    if (tid == 0) {
        #pragma unroll
        for (int s = 0; s < 3; ++s) {
            asm volatile("mbarrier.init.shared.b64 [%0], 1;" :: "r"(mbarb + 8u * s) : "memory");
            asm volatile("mbarrier.init.shared.b64 [%0], 8;" :: "r"(mbarb + 24u + 8u * s) : "memory");
        }
    }
    __syncthreads();

    // -------- tick 0: v = 0 + ext --------
    for (int i = tid; i < 128 * 64; i += NTHR) {
        int r = i >> 6, c = i & 63;
        float cc   = g_ext[m][bm0 + r][bn0 + c];
        float vnew = __fadd_rn(0.0f, cc);
        float u    = __fadd_rn(vnew, -1.0f);
        bool  sp   = (u >= 0.0f);
        sv[r * VSTR + c] = sp ? 0.0f : vnew;
        write_spike(0, m, bm0 + r, bn0 + c, sp);
    }

    // spike-count accumulator in registers (thread-owned elements)
    unsigned pack[8];
    #pragma unroll
    for (int q = 0; q < 8; ++q) {
        pack[q] = 0u;
        float4 e4 = __ldg(&xp[q * 256]);
        const float* ep = &e4.x;
        #pragma unroll
        for (int f = 0; f < 4; ++f) {
            float vnew = __fadd_rn(0.0f, ep[f]);
            float u    = __fadd_rn(vnew, -1.0f);
            if (u >= 0.0f) pack[q] += (1u << (8 * f));
        }
    }
    grid_barrier(1);

    const int r15   = lane & 15;
    const int kh16  = (lane >> 4) * 16;
    const unsigned swl = (((unsigned)r15 & 7u) << 4);

    unsigned fful = 0, ew = 0, fu = 0x7;

    for (int t = 1; t < 16; ++t) {
        const int rbuf = (t - 1) & 1, wbuf = t & 1;

        auto issue_stage = [&](int s) {        // tid 0 only
            int slot = s % 3;
            unsigned bit = 1u << slot;
            if (fu & bit) fu &= ~bit;
            else { mbar_wait(mbarb + 24u + 8u * slot, (ew >> slot) & 1u); ew ^= bit; }
            unsigned mb = mbarb + 8u * slot;
            mbar_expect(mb, SLOT_A + SLOT_B);
            unsigned sbase = smb + (unsigned)slot * SLOTSZ;
            bulk_ld(sbase,          &g_Abuf[rbuf][m][s][bm0][0], SLOT_A, mb);
            bulk_ld(sbase + SLOT_A, &g_Wbig[m][s][bn0][0],       SLOT_B, mb);
        };

        if (tid == 0) {
            asm volatile("fence.proxy.async;" ::: "memory");
            issue_stage(0); issue_stage(1); issue_stage(2);
        }

        float c0[2][4][4], c1[2][4][4];
        #pragma unroll
        for (int a = 0; a < 2; ++a)
            #pragma unroll
            for (int b = 0; b < 4; ++b)
                #pragma unroll
                for (int f = 0; f < 4; ++f) { c0[a][b][f] = 0.f; c1[a][b][f] = 0.f; }

        for (int s = 0; s < NS; ++s) {
            int slot = s % 3;
            mbar_wait(mbarb + 8u * slot, (fful >> slot) & 1u);
            fful ^= (1u << slot);

            bool own = (s < OWN_STG);
            unsigned abase = smb + (unsigned)slot * SLOTSZ;
            unsigned bbase = abase + SLOT_A;
            #pragma unroll
            for (int kk = 0; kk < 4; ++kk) {
                unsigned a[2][4], bfr[2][4];
                unsigned coff = ((unsigned)(kk * 32 + kh16)) ^ swl;
                #pragma unroll
                for (int im = 0; im < 2; ++im)
                    ldm4(a[im], abase + (unsigned)((wm * 32 + im * 16 + r15) * 128) + coff);
                #pragma unroll
                for (int ib = 0; ib < 2; ++ib)
                    ldm4(bfr[ib], bbase + (unsigned)((wn * 32 + ib * 16 + r15) * 128) + coff);
                if (own) {
                    #pragma unroll
                    for (int im = 0; im < 2; ++im)
                        #pragma unroll
                        for (int in = 0; in < 4; ++in) {
                            int ib = in >> 1, sub = in & 1;
                            mma16816(c0[im][in], a[im], bfr[ib][sub], bfr[ib][sub + 2]);
                        }
                } else {
                    #pragma unroll
                    for (int im = 0; im < 2; ++im)
                        #pragma unroll
                        for (int in = 0; in < 4; ++in) {
                            int ib = in >> 1, sub = in & 1;
                            mma16816(c1[im][in], a[im], bfr[ib][sub], bfr[ib][sub + 2]);
                        }
                }
            }
            if (lane == 0) mbar_arrive(mbarb + 24u + 8u * slot);   // warp done with slot
            if (tid == 0 && s + 3 < NS) issue_stage(s + 3);
        }

        // -------- epilogue: LIF (bitwise chain) + scattered spike STGs --------
        float4 e4 = __ldg(&xp[0]);
        #pragma unroll
        for (int q = 0; q < 8; ++q) {
            float4 e4n;
            if (q < 7) e4n = __ldg(&xp[(q + 1) * 256]);
            int im = q >> 2, in = q & 3;
            const float* ep = &e4.x;
            #pragma unroll
            for (int f = 0; f < 4; ++f) {
                int r = wm * 32 + im * 16 + (lane >> 2) + (f >> 1) * 8;
                int c = wn * 32 + in * 8 + (lane & 3) * 2 + (f & 1);
                int gc = bn0 + c;
                int ci = (int)c0[im][in][f];
                int rr = ci & 8191;
                int aEi = (rr < 4096) ? rr : rr - 8192;
                int aIi = (ci - aEi) >> 13;
                float t1   = __fadd_rn(ep[f], c1[im][in][f]);
                float t2   = __fadd_rn(t1, (float)aEi);
                float cur  = __fadd_rn(t2, (float)aIi);
                float vold = sv[r * VSTR + c];
                float dec  = (gc < NEx) ? 0.5f : decayI;
                float vnew = __fadd_rn(__fmul_rn(vold, dec), cur);
                float u    = __fadd_rn(vnew, -1.0f);
                bool  sp   = (u >= 0.0f);
                sv[r * VSTR + c] = sp ? 0.0f : vnew;
                if (sp) pack[q] += (1u << (8 * f));
                write_spike(wbuf, m, bm0 + r, gc, sp);
            }
            e4 = e4n;
        }

        if (t < 15) grid_barrier((unsigned)(t + 1));
    }

    // -------- final: write spike counts from registers --------
    #pragma unroll
    for (int q = 0; q < 8; ++q) {
        int im = q >> 2, in = q & 3;
        #pragma unroll
        for (int f = 0; f < 4; ++f) {
            int r = wm * 32 + im * 16 + (lane >> 2) + (f >> 1) * 8;
            int c = wn * 32 + in * 8 + (lane & 3) * 2 + (f & 1);
            unsigned cnt = (pack[q] >> (8 * f)) & 255u;
            dout[(long long)(bm0 + r) * (MESH * NN) + m * NN + bn0 + c] = (float)cnt;
        }
    }
}

// ---------------- launch ----------------
extern "C" void kernel_launch(void* const* d_in, const int* in_sizes, int n_in,
                              void* d_out, int out_size) {
    const float* x       = (const float*)d_in[0];
    const float* W_in    = (const float*)d_in[1];
    const float* b_in    = (const float*)d_in[2];
    const float* W_inter = (const float*)d_in[3];
    const float* W_EE    = (const float*)d_in[4];
    const float* W_EI    = (const float*)d_in[5];
    const float* W_IE    = (const float*)d_in[6];
    const float* W_II    = (const float*)d_in[7];
    float* out = (float*)d_out;
    const float decayI = (float)(1.0 - 1.0 / 1.5);

    cudaFuncSetAttribute(k_persist, cudaFuncAttributeMaxDynamicSharedMemorySize, SM_DYN);

    // local launch idx 3 == k_persist (ncu capture slot)
    k_init<<<2048, 256>>>(W_in, W_inter, W_EE, W_EI, W_IE, W_II);   // 0
    k_ext<<<dim3(BB / EXT_BT, MESH), 512>>>(x, b_in);               // 1
    k_perm<<<1024, 256>>>();                                        // 2
    dim3 grid(8, 4, 8);                                             // 256 CTAs, 2/SM
    k_persist<<<grid, NTHR, SM_DYN>>>(out, decayI);                 // 3
}

// round 14
// speedup vs baseline: 1.0327x; 1.0327x over previous
#include <cuda_runtime.h>
#include <cuda_bf16.h>

#define MESH 8
#define NN   512
#define NEx  409
#define NIx  103
#define DD   243
#define BB   512
// K layout: [0,448) own E, [448,576) own I (weights x8192), [576,1024) prev-mesh E.
// Stage-major storage, 16 stages of 64 k (128B swizzled rows).
#define KT      1024
#define K_ISEC  448
#define K_PSEC  576
#define ISCALE  8192.0f
#define NS      16
#define OWN_STG 9
#define NTHR    512
#define SLOT    16384u

// ---------------- device state (stage-major, SW128-swizzled 128B rows) ----------------
__device__ __align__(16) __nv_bfloat16 g_Wbig[MESH][NS][NN][64];
__device__ __align__(16) __nv_bfloat16 g_Abuf[2][MESH][NS][BB][64];
__device__ float g_WinT[MESH][DD][NN];
__device__ float g_ext[MESH][BB][NN];
__device__ unsigned g_bar[4];          // one barrier counter per batch-tile group

__device__ __forceinline__ float quantw(float w) {
    float q = rintf(w);                  // round-half-even == jnp.round
    return fminf(7.f, fmaxf(-8.f, q));
}

// ---------------- combined init (zero + Wbig + WinT) ----------------
__global__ void k_init(const float* __restrict__ W_in, const float* __restrict__ W_inter,
                       const float* __restrict__ W_EE, const float* __restrict__ W_EI,
                       const float* __restrict__ W_IE, const float* __restrict__ W_II) {
    long long stride = (long long)gridDim.x * blockDim.x;
    long long i0 = (long long)blockIdx.x * blockDim.x + threadIdx.x;
    if (i0 < 4) g_bar[i0] = 0u;

    unsigned* A = (unsigned*)&g_Abuf[0][0][0][0][0];
    long long nA = 2LL * MESH * BB * KT / 2;
    for (long long i = i0; i < nA; i += stride) A[i] = 0u;

    long long totW = (long long)MESH * NN * KT;
    for (long long idx = i0; idx < totW; idx += stride) {
        int k = (int)(idx % KT);
        int n = (int)((idx / KT) % NN);
        int m = (int)(idx / ((long long)KT * NN));
        float w = 0.f;
        if (k < K_ISEC) {                        // E-driven: W_EE / W_EI
            if (k < NEx)
                w = (n < NEx) ? W_EE[((long long)m * NEx + n) * NEx + k]
                              : W_EI[((long long)m * NIx + (n - NEx)) * NEx + k];
            w = quantw(w);
        } else if (k < K_PSEC) {                 // I-driven, packed *8192 (exact in bf16)
            int ki = k - K_ISEC;
            if (ki < NIx)
                w = (n < NEx) ? W_IE[((long long)m * NEx + n) * NIx + ki]
                              : W_II[((long long)m * NIx + (n - NEx)) * NIx + ki];
            w = quantw(w) * ISCALE;
        } else {                                 // inter: mesh m receives W_inter[m-1]
            int kp = k - K_PSEC;
            if (kp < NEx) {
                int mp = (m + MESH - 1) % MESH;
                w = W_inter[((long long)mp * NN + n) * NEx + kp];
            }
            w = quantw(w);
        }
        int st = k >> 6, kk = k & 63;
        unsigned off = ((unsigned)(2 * kk)) ^ (((unsigned)n & 7u) << 4);   // SW128 within row
        *(__nv_bfloat16*)((char*)&g_Wbig[m][st][n][0] + off) = __float2bfloat16(w);
    }

    long long totI = (long long)MESH * NN * DD;
    for (long long idx = i0; idx < totI; idx += stride) {
        int d = (int)(idx % DD);
        int n = (int)((idx / DD) % NN);
        int m = (int)(idx / ((long long)DD * NN));
        g_WinT[m][d][n] = quantw(W_in[idx]);
    }
}

// ---------------- ext_proj: f32x2 packed serial-d FMA (per-half bitwise == scalar) ------
#define EXT_BT 16
__device__ __forceinline__ unsigned long long fma2(unsigned long long a, unsigned long long b,
                                                   unsigned long long c) {
    unsigned long long d;
    asm("fma.rn.f32x2 %0, %1, %2, %3;" : "=l"(d) : "l"(a), "l"(b), "l"(c));
    return d;
}
__global__ void __launch_bounds__(512)
k_ext(const float* __restrict__ X, const float* __restrict__ b_in) {
    __shared__ __align__(16) float sx[DD][EXT_BT];
    const int m  = blockIdx.y;
    const int b0 = blockIdx.x * EXT_BT;
    const int n  = threadIdx.x;
    for (int i = threadIdx.x; i < EXT_BT * DD; i += 512) {
        int bb = i / DD, d = i % DD;
        sx[d][bb] = X[(long long)(b0 + bb) * DD + d];
    }
    __syncthreads();
    unsigned long long acc2[8];
    #pragma unroll
    for (int q = 0; q < 8; ++q) acc2[q] = 0ull;
    for (int d = 0; d < DD; ++d) {
        float w = g_WinT[m][d][n];
        unsigned long long w2;
        asm("mov.b64 %0, {%1,%1};" : "=l"(w2) : "r"(__float_as_uint(w)));
        const unsigned long long* p = reinterpret_cast<const unsigned long long*>(&sx[d][0]);
        #pragma unroll
        for (int q = 0; q < 8; ++q) acc2[q] = fma2(p[q], w2, acc2[q]);
    }
    float bi = b_in[m * NN + n];
    #pragma unroll
    for (int q = 0; q < 8; ++q) {
        unsigned lo, hi;
        asm("mov.b64 {%0,%1}, %2;" : "=r"(lo), "=r"(hi) : "l"(acc2[q]));
        g_ext[m][b0 + 2 * q][n]     = __fadd_rn(__uint_as_float(lo), bi);
        g_ext[m][b0 + 2 * q + 1][n] = __fadd_rn(__uint_as_float(hi), bi);
    }
}

__global__ void k_dummy() {}

// ---------------- asm helpers ----------------
__device__ __forceinline__ void ldm4(unsigned* r, unsigned addr) {
    asm volatile("ldmatrix.sync.aligned.m8n8.x4.shared.b16 {%0,%1,%2,%3}, [%4];\n"
                 : "=r"(r[0]), "=r"(r[1]), "=r"(r[2]), "=r"(r[3]) : "r"(addr));
}
__device__ __forceinline__ void mma16816(float* c, const unsigned* a, unsigned b0, unsigned b1) {
    asm volatile("mma.sync.aligned.m16n8k16.row.col.f32.bf16.bf16.f32 "
                 "{%0,%1,%2,%3}, {%4,%5,%6,%7}, {%8,%9}, {%0,%1,%2,%3};\n"
                 : "+f"(c[0]), "+f"(c[1]), "+f"(c[2]), "+f"(c[3])
                 : "r"(a[0]), "r"(a[1]), "r"(a[2]), "r"(a[3]), "r"(b0), "r"(b1));
}
__device__ __forceinline__ void bulk_ld(unsigned dst, const void* src, unsigned bytes,
                                        unsigned mbar) {
    asm volatile("cp.async.bulk.shared::cluster.global.mbarrier::complete_tx::bytes "
                 "[%0], [%1], %2, [%3];"
                 :: "r"(dst), "l"(src), "r"(bytes), "r"(mbar) : "memory");
}
__device__ __forceinline__ void mbar_expect(unsigned mbar, unsigned bytes) {
    asm volatile("mbarrier.arrive.expect_tx.shared.b64 _, [%0], %1;"
                 :: "r"(mbar), "r"(bytes) : "memory");
}
__device__ __forceinline__ void mbar_arrive(unsigned mbar) {
    asm volatile("mbarrier.arrive.shared.b64 _, [%0];" :: "r"(mbar) : "memory");
}
__device__ __forceinline__ void mbar_wait(unsigned addr, unsigned parity) {
    unsigned done;
    do {
        asm volatile(
            "{\n\t.reg .pred p;\n\t"
            "mbarrier.try_wait.parity.shared.b64 p, [%1], %2, 0x989680;\n\t"
            "selp.b32 %0, 1, 0, p;\n\t}"
            : "=r"(done) : "r"(addr), "r"(parity) : "memory");
    } while (!done);
}

// batch-group barrier: 32 CTAs sharing blockIdx.y
__device__ __forceinline__ void grid_barrier(unsigned phase, int bt) {
    __syncthreads();
    if (threadIdx.x == 0) {
        asm volatile("red.release.gpu.global.add.u32 [%0], %1;"
                     :: "l"(&g_bar[bt]), "r"(1u) : "memory");
        unsigned target = phase * 32u, v;
        do {
            asm volatile("ld.acquire.gpu.global.u32 %0, [%1];"
                         : "=r"(v) : "l"(&g_bar[bt]) : "memory");
            if (v < target) __nanosleep(64);
        } while (v < target);
    }
    __syncthreads();
}

// scattered spike write (stage-major + SW128 swizzle)
__device__ __forceinline__ void write_spike(int wbuf, int m, int grow, int gc, bool sp) {
    unsigned short h = sp ? 0x3F80 : 0;
    unsigned sw = (((unsigned)grow & 7u) << 4);
    int kown = (gc < NEx) ? gc : (gc + (K_ISEC - NEx));
    int st = kown >> 6, kk = kown & 63;
    *(unsigned short*)((char*)&g_Abuf[wbuf][m][st][grow][0] + (((unsigned)(2 * kk)) ^ sw)) = h;
    if (gc < NEx) {
        int kp = K_PSEC + gc;
        *(unsigned short*)((char*)&g_Abuf[wbuf][(m + 1) & 7][kp >> 6][grow][0]
                           + (((unsigned)(2 * (kp & 63))) ^ sw)) = h;
    }
}

// ---------------- persistent bf16-HMMA reservoir (R12 shape + B-prefetch) -------------
// smem: slots 3x(A16K+B16K)=96K | v f32 stride 132 | ext f32 stride 129 | mbars
#define SMO_V    98304
#define SMO_E    165888
#define SMO_MBAR 231936
#define SM_DYN   232064

__global__ void __launch_bounds__(NTHR, 1)
k_persist(float* __restrict__ dout, float decayI) {
    extern __shared__ __align__(16) char sm[];
    float* sv = (float*)(sm + SMO_V);    // stride 132
    float* se = (float*)(sm + SMO_E);    // stride 129

    const int m   = blockIdx.z;
    const int bt  = blockIdx.y;
    const int bm0 = bt * 128;
    const int bn0 = blockIdx.x * 128;
    const int tid  = threadIdx.x;
    const int lane = tid & 31, warp = tid >> 5;
    const int wm = warp >> 2, wn = warp & 3;      // 4x4 warps, warp tile 32x32

    unsigned smb   = (unsigned)__cvta_generic_to_shared(sm);
    unsigned mbarb = smb + SMO_MBAR;              // full: +0,8,16 ; empty: +24,32,40

    if (tid == 0) {
        #pragma unroll
        for (int s = 0; s < 3; ++s) {
            asm volatile("mbarrier.init.shared.b64 [%0], 2;"  :: "r"(mbarb + 8u * s) : "memory");
            asm volatile("mbarrier.init.shared.b64 [%0], 16;" :: "r"(mbarb + 24u + 8u * s) : "memory");
        }
    }
    __syncthreads();

    // -------- load ext tile into smem ONCE, coalesced --------
    for (int i = tid; i < 128 * 128; i += NTHR) {
        int r = i >> 7, c = i & 127;
        se[r * 129 + c] = g_ext[m][bm0 + r][bn0 + c];
    }
    __syncthreads();

    // -------- tick 0: v = 0 + ext --------
    for (int i = tid; i < 128 * 128; i += NTHR) {
        int r = i >> 7, c = i & 127;
        float cc   = se[r * 129 + c];
        float vnew = __fadd_rn(0.0f, cc);
        float u    = __fadd_rn(vnew, -1.0f);
        bool  sp   = (u >= 0.0f);
        sv[r * 132 + c] = sp ? 0.0f : vnew;
        write_spike(0, m, bm0 + r, bn0 + c, sp);
    }

    // spike-count accumulator in registers (thread-owned elements)
    unsigned pack[8];
    #pragma unroll
    for (int q = 0; q < 8; ++q) pack[q] = 0u;
    #pragma unroll
    for (int im = 0; im < 2; ++im)
        #pragma unroll
        for (int in = 0; in < 4; ++in)
            #pragma unroll
            for (int f = 0; f < 4; ++f) {
                int r = wm * 32 + im * 16 + (lane >> 2) + (f >> 1) * 8;
                int c = wn * 32 + in * 8 + (lane & 3) * 2 + (f & 1);
                float vnew = __fadd_rn(0.0f, se[r * 129 + c]);
                float u    = __fadd_rn(vnew, -1.0f);
                int idx = im * 16 + in * 4 + f;
                if (u >= 0.0f) pack[idx >> 2] += (1u << (8 * (idx & 3)));
            }
    grid_barrier(1, bt);

    const int r15   = lane & 15;
    const int kh16  = (lane >> 4) * 16;
    const unsigned swl = (((unsigned)r15 & 7u) << 4);

    unsigned fful = 0, ew = 0;

    // initial fill: full A+B for stages 0..2 of tick 1 (slots fresh, no empty wait)
    if (tid == 0) {
        asm volatile("fence.proxy.async;" ::: "memory");
        #pragma unroll
        for (int s = 0; s < 3; ++s) {
            unsigned mb = mbarb + 8u * s;
            unsigned sbase = smb + (unsigned)s * 32768u;
            mbar_expect(mb, SLOT);
            bulk_ld(sbase, &g_Abuf[0][m][s][bm0][0], SLOT, mb);
            mbar_expect(mb, SLOT);
            bulk_ld(sbase + SLOT, &g_Wbig[m][s][bn0][0], SLOT, mb);
        }
    }

    for (int t = 1; t < 16; ++t) {
        const int rbuf = (t - 1) & 1, wbuf = t & 1;

        float c0[2][4][4], c1[2][4][4];
        #pragma unroll
        for (int a = 0; a < 2; ++a)
            #pragma unroll
            for (int b = 0; b < 4; ++b)
                #pragma unroll
                for (int f = 0; f < 4; ++f) { c0[a][b][f] = 0.f; c1[a][b][f] = 0.f; }

        for (int s = 0; s < NS; ++s) {
            int slot = s % 3;
            mbar_wait(mbarb + 8u * slot, (fful >> slot) & 1u);
            fful ^= (1u << slot);

            bool own = (s < OWN_STG);
            unsigned abase = smb + (unsigned)slot * 32768u;
            unsigned bbase = abase + SLOT;
            #pragma unroll
            for (int kk = 0; kk < 4; ++kk) {
                unsigned a[2][4], bfr[2][4];
                unsigned coff = ((unsigned)(kk * 32 + kh16)) ^ swl;
                #pragma unroll
                for (int im = 0; im < 2; ++im)
                    ldm4(a[im], abase + (unsigned)((wm * 32 + im * 16 + r15) * 128) + coff);
                #pragma unroll
                for (int ib = 0; ib < 2; ++ib)
                    ldm4(bfr[ib], bbase + (unsigned)((wn * 32 + ib * 16 + r15) * 128) + coff);
                if (own) {
                    #pragma unroll
                    for (int im = 0; im < 2; ++im)
                        #pragma unroll
                        for (int in = 0; in < 4; ++in) {
                            int ib = in >> 1, sub = in & 1;
                            mma16816(c0[im][in], a[im], bfr[ib][sub], bfr[ib][sub + 2]);
                        }
                } else {
                    #pragma unroll
                    for (int im = 0; im < 2; ++im)
                        #pragma unroll
                        for (int in = 0; in < 4; ++in) {
                            int ib = in >> 1, sub = in & 1;
                            mma16816(c1[im][in], a[im], bfr[ib][sub], bfr[ib][sub + 2]);
                        }
                }
            }
            if (lane == 0) mbar_arrive(mbarb + 24u + 8u * slot);   // warp done with slot

            // in-loop issue of stage s+3 (A for THIS tick + B): empty-wait then 2 expects
            if (tid == 0 && s + 3 < NS) {
                int s2 = s + 3, sl2 = s2 % 3;
                mbar_wait(mbarb + 24u + 8u * sl2, (ew >> sl2) & 1u); ew ^= (1u << sl2);
                unsigned mb = mbarb + 8u * sl2;
                unsigned sbase = smb + (unsigned)sl2 * 32768u;
                mbar_expect(mb, SLOT);
                bulk_ld(sbase, &g_Abuf[rbuf][m][s2][bm0][0], SLOT, mb);
                mbar_expect(mb, SLOT);
                bulk_ld(sbase + SLOT, &g_Wbig[m][s2][bn0][0], SLOT, mb);
            }
        }

        // -------- B-prefetch for next tick's stages 0..2 (weights: no barrier needed) --
        if (tid == 0 && t < 15) {
            #pragma unroll
            for (int s = 0; s < 3; ++s) {
                mbar_wait(mbarb + 24u + 8u * s, (ew >> s) & 1u); ew ^= (1u << s);
                unsigned mb = mbarb + 8u * s;
                mbar_expect(mb, SLOT);
                bulk_ld(smb + (unsigned)s * 32768u + SLOT, &g_Wbig[m][s][bn0][0], SLOT, mb);
            }
        }

        // -------- epilogue: LIF (bitwise chain) + scattered spike STGs --------
        #pragma unroll
        for (int im = 0; im < 2; ++im)
            #pragma unroll
            for (int in = 0; in < 4; ++in)
                #pragma unroll
                for (int f = 0; f < 4; ++f) {
                    int r = wm * 32 + im * 16 + (lane >> 2) + (f >> 1) * 8;
                    int c = wn * 32 + in * 8 + (lane & 3) * 2 + (f & 1);
                    int gc = bn0 + c;
                    int ci = (int)c0[im][in][f];
                    int rr = ci & 8191;
                    int aEi = (rr < 4096) ? rr : rr - 8192;
                    int aIi = (ci - aEi) >> 13;
                    float ext  = se[r * 129 + c];
                    float t1   = __fadd_rn(ext, c1[im][in][f]);
                    float t2   = __fadd_rn(t1, (float)aEi);
                    float cur  = __fadd_rn(t2, (float)aIi);
                    float vold = sv[r * 132 + c];
                    float dec  = (gc < NEx) ? 0.5f : decayI;
                    float vnew = __fadd_rn(__fmul_rn(vold, dec), cur);
                    float u    = __fadd_rn(vnew, -1.0f);
                    bool  sp   = (u >= 0.0f);
                    sv[r * 132 + c] = sp ? 0.0f : vnew;
                    int idx = im * 16 + in * 4 + f;
                    if (sp) pack[idx >> 2] += (1u << (8 * (idx & 3)));
                    write_spike(wbuf, m, bm0 + r, gc, sp);
                }

        if (t < 15) {
            grid_barrier((unsigned)(t + 1), bt);
            // A halves for next tick's stages 0..2 (spikes now globally visible)
            if (tid == 0) {
                #pragma unroll
                for (int s = 0; s < 3; ++s) {
                    unsigned mb = mbarb + 8u * s;
                    mbar_expect(mb, SLOT);
                    bulk_ld(smb + (unsigned)s * 32768u, &g_Abuf[wbuf][m][s][bm0][0], SLOT, mb);
                }
            }
        }
    }

    // -------- final: write spike counts from registers --------
    #pragma unroll
    for (int im = 0; im < 2; ++im)
        #pragma unroll
        for (int in = 0; in < 4; ++in)
            #pragma unroll
            for (int f = 0; f < 4; ++f) {
                int r = wm * 32 + im * 16 + (lane >> 2) + (f >> 1) * 8;
                int c = wn * 32 + in * 8 + (lane & 3) * 2 + (f & 1);
                int idx = im * 16 + in * 4 + f;
                unsigned cnt = (pack[idx >> 2] >> (8 * (idx & 3))) & 255u;
                dout[(long long)(bm0 + r) * (MESH * NN) + m * NN + bn0 + c] = (float)cnt;
            }
}

// ---------------- launch ----------------
extern "C" void kernel_launch(void* const* d_in, const int* in_sizes, int n_in,
                              void* d_out, int out_size) {
    const float* x       = (const float*)d_in[0];
    const float* W_in    = (const float*)d_in[1];
    const float* b_in    = (const float*)d_in[2];
    const float* W_inter = (const float*)d_in[3];
    const float* W_EE    = (const float*)d_in[4];
    const float* W_EI    = (const float*)d_in[5];
    const float* W_IE    = (const float*)d_in[6];
    const float* W_II    = (const float*)d_in[7];
    float* out = (float*)d_out;
    const float decayI = (float)(1.0 - 1.0 / 1.5);

    cudaFuncSetAttribute(k_persist, cudaFuncAttributeMaxDynamicSharedMemorySize, SM_DYN);

    // local launch idx 3 == k_persist (ncu capture slot)
    k_init<<<2048, 256>>>(W_in, W_inter, W_EE, W_EI, W_IE, W_II);   // 0
    k_ext<<<dim3(BB / EXT_BT, MESH), 512>>>(x, b_in);               // 1
    k_dummy<<<1, 1>>>();                                            // 2
    dim3 grid(4, 4, 8);                                             // 128 CTAs, 1/SM
    k_persist<<<grid, NTHR, SM_DYN>>>(out, decayI);                 // 3
}

// round 15
// speedup vs baseline: 1.2800x; 1.2395x over previous
#include <cuda_runtime.h>
#include <cuda_bf16.h>

#define MESH 8
#define NN   512
#define NEx  409
#define NIx  103
#define DD   243
#define BB   512
// K layout: [0,448) own E, [448,576) own I (weights x8192), [576,1024) prev-mesh E.
// Stage-major storage, 16 stages of 64 k (128B swizzled rows).
#define KT      1024
#define K_ISEC  448
#define K_PSEC  576
#define ISCALE  8192.0f
#define NS      16
#define OWN_STG 9
#define NTHR    512
#define SLOT    16384u

// ---------------- device state (stage-major, SW128-swizzled 128B rows) ----------------
__device__ __align__(16) __nv_bfloat16 g_Wbig[MESH][NS][NN][64];
__device__ __align__(16) __nv_bfloat16 g_Abuf[2][MESH][NS][BB][64];
__device__ float g_WinT[MESH][DD][NN];
__device__ float g_ext[MESH][BB][NN];
__device__ unsigned g_bar;

__device__ __forceinline__ float quantw(float w) {
    float q = rintf(w);                  // round-half-even == jnp.round
    return fminf(7.f, fmaxf(-8.f, q));
}

// ---------------- combined init (zero + Wbig + WinT), vectorized ----------------
__global__ void k_init(const float* __restrict__ W_in, const float* __restrict__ W_inter,
                       const float* __restrict__ W_EE, const float* __restrict__ W_EI,
                       const float* __restrict__ W_IE, const float* __restrict__ W_II) {
    long long stride = (long long)gridDim.x * blockDim.x;
    long long i0 = (long long)blockIdx.x * blockDim.x + threadIdx.x;
    if (i0 == 0) g_bar = 0u;

    // zero spike buffers with 16B stores
    uint4 z; z.x = z.y = z.z = z.w = 0u;
    uint4* A4 = (uint4*)&g_Abuf[0][0][0][0][0];
    long long nA4 = 2LL * MESH * BB * KT * 2 / 16;
    for (long long i = i0; i < nA4; i += stride) A4[i] = z;

    // Wbig: 8 consecutive k per 16B store (swizzle is 16B-granular)
    long long totW = (long long)MESH * NN * (KT / 8);
    for (long long idx = i0; idx < totW; idx += stride) {
        int kg = (int)(idx % (KT / 8));
        int n  = (int)((idx / (KT / 8)) % NN);
        int m  = (int)(idx / ((long long)(KT / 8) * NN));
        int k0 = kg * 8;
        __nv_bfloat16 buf8[8];
        #pragma unroll
        for (int j = 0; j < 8; ++j) {
            int k = k0 + j;
            float w = 0.f;
            if (k < K_ISEC) {                        // E-driven: W_EE / W_EI
                if (k < NEx)
                    w = (n < NEx) ? W_EE[((long long)m * NEx + n) * NEx + k]
                                  : W_EI[((long long)m * NIx + (n - NEx)) * NEx + k];
                w = quantw(w);
            } else if (k < K_PSEC) {                 // I-driven, packed *8192 (exact in bf16)
                int ki = k - K_ISEC;
                if (ki < NIx)
                    w = (n < NEx) ? W_IE[((long long)m * NEx + n) * NIx + ki]
                                  : W_II[((long long)m * NIx + (n - NEx)) * NIx + ki];
                w = quantw(w) * ISCALE;
            } else {                                 // inter: mesh m receives W_inter[m-1]
                int kp = k - K_PSEC;
                if (kp < NEx) {
                    int mp = (m + MESH - 1) % MESH;
                    w = W_inter[((long long)mp * NN + n) * NEx + kp];
                }
                w = quantw(w);
            }
            buf8[j] = __float2bfloat16(w);
        }
        int st = k0 >> 6, kk = k0 & 63;
        unsigned off = ((unsigned)(2 * kk)) ^ (((unsigned)n & 7u) << 4);
        *(uint4*)((char*)&g_Wbig[m][st][n][0] + off) = *(uint4*)buf8;
    }

    long long totI = (long long)MESH * NN * DD;
    for (long long idx = i0; idx < totI; idx += stride) {
        int d = (int)(idx % DD);
        int n = (int)((idx / DD) % NN);
        int m = (int)(idx / ((long long)DD * NN));
        g_WinT[m][d][n] = quantw(W_in[idx]);
    }
}

// ---------------- ext_proj: f32x2 packed serial-d FMA (per-half bitwise == scalar) ------
#define EXT_BT 16
__device__ __forceinline__ unsigned long long fma2(unsigned long long a, unsigned long long b,
                                                   unsigned long long c) {
    unsigned long long d;
    asm("fma.rn.f32x2 %0, %1, %2, %3;" : "=l"(d) : "l"(a), "l"(b), "l"(c));
    return d;
}
__global__ void __launch_bounds__(512)
k_ext(const float* __restrict__ X, const float* __restrict__ b_in) {
    __shared__ __align__(16) float sx[DD][EXT_BT];
    const int m  = blockIdx.y;
    const int b0 = blockIdx.x * EXT_BT;
    const int n  = threadIdx.x;
    for (int i = threadIdx.x; i < EXT_BT * DD; i += 512) {
        int bb = i / DD, d = i % DD;
        sx[d][bb] = X[(long long)(b0 + bb) * DD + d];
    }
    __syncthreads();
    unsigned long long acc2[8];
    #pragma unroll
    for (int q = 0; q < 8; ++q) acc2[q] = 0ull;
    for (int d = 0; d < DD; ++d) {
        float w = g_WinT[m][d][n];
        unsigned long long w2;
        asm("mov.b64 %0, {%1,%1};" : "=l"(w2) : "r"(__float_as_uint(w)));
        const unsigned long long* p = reinterpret_cast<const unsigned long long*>(&sx[d][0]);
        #pragma unroll
        for (int q = 0; q < 8; ++q) acc2[q] = fma2(p[q], w2, acc2[q]);
    }
    float bi = b_in[m * NN + n];
    #pragma unroll
    for (int q = 0; q < 8; ++q) {
        unsigned lo, hi;
        asm("mov.b64 {%0,%1}, %2;" : "=r"(lo), "=r"(hi) : "l"(acc2[q]));
        g_ext[m][b0 + 2 * q][n]     = __fadd_rn(__uint_as_float(lo), bi);
        g_ext[m][b0 + 2 * q + 1][n] = __fadd_rn(__uint_as_float(hi), bi);
    }
}

__global__ void k_dummy() {}

// ---------------- asm helpers ----------------
__device__ __forceinline__ void ldm4(unsigned* r, unsigned addr) {
    asm volatile("ldmatrix.sync.aligned.m8n8.x4.shared.b16 {%0,%1,%2,%3}, [%4];\n"
                 : "=r"(r[0]), "=r"(r[1]), "=r"(r[2]), "=r"(r[3]) : "r"(addr));
}
__device__ __forceinline__ void mma16816(float* c, const unsigned* a, unsigned b0, unsigned b1) {
    asm volatile("mma.sync.aligned.m16n8k16.row.col.f32.bf16.bf16.f32 "
                 "{%0,%1,%2,%3}, {%4,%5,%6,%7}, {%8,%9}, {%0,%1,%2,%3};\n"
                 : "+f"(c[0]), "+f"(c[1]), "+f"(c[2]), "+f"(c[3])
                 : "r"(a[0]), "r"(a[1]), "r"(a[2]), "r"(a[3]), "r"(b0), "r"(b1));
}
__device__ __forceinline__ void bulk_ld(unsigned dst, const void* src, unsigned bytes,
                                        unsigned mbar) {
    asm volatile("cp.async.bulk.shared::cluster.global.mbarrier::complete_tx::bytes "
                 "[%0], [%1], %2, [%3];"
                 :: "r"(dst), "l"(src), "r"(bytes), "r"(mbar) : "memory");
}
__device__ __forceinline__ void bulk_st(void* gdst, unsigned ssrc) {
    asm volatile("cp.async.bulk.global.shared::cta.bulk_group [%0], [%1], %2;"
                 :: "l"(gdst), "r"(ssrc), "r"(SLOT) : "memory");
}
__device__ __forceinline__ void mbar_expect(unsigned mbar, unsigned bytes) {
    asm volatile("mbarrier.arrive.expect_tx.shared.b64 _, [%0], %1;"
                 :: "r"(mbar), "r"(bytes) : "memory");
}
__device__ __forceinline__ void mbar_wait(unsigned addr, unsigned parity) {
    unsigned done;
    do {
        asm volatile(
            "{\n\t.reg .pred p;\n\t"
            "mbarrier.try_wait.parity.shared.b64 p, [%1], %2, 0x989680;\n\t"
            "selp.b32 %0, 1, 0, p;\n\t}"
            : "=r"(done) : "r"(addr), "r"(parity) : "memory");
    } while (!done);
}

__device__ __forceinline__ void grid_barrier(unsigned phase) {
    __threadfence();
    __syncthreads();
    if (threadIdx.x == 0) {
        asm volatile("red.release.gpu.global.add.u32 [%0], %1;" :: "l"(&g_bar), "r"(1u) : "memory");
        unsigned target = phase * 128u, v;
        do {
            asm volatile("ld.acquire.gpu.global.u32 %0, [%1];" : "=r"(v) : "l"(&g_bar) : "memory");
            if (v < target) __nanosleep(64);
        } while (v < target);
    }
    __syncthreads();
}

// scattered spike write (tick 0 only)
__device__ __forceinline__ void write_spike0(int m, int grow, int gc, bool sp) {
    unsigned short h = sp ? 0x3F80 : 0;
    unsigned sw = (((unsigned)grow & 7u) << 4);
    int kown = (gc < NEx) ? gc : (gc + (K_ISEC - NEx));
    int st = kown >> 6, kk = kown & 63;
    *(unsigned short*)((char*)&g_Abuf[0][m][st][grow][0] + (((unsigned)(2 * kk)) ^ sw)) = h;
    if (gc < NEx) {
        int kp = K_PSEC + gc;
        *(unsigned short*)((char*)&g_Abuf[0][(m + 1) & 7][kp >> 6][grow][0]
                           + (((unsigned)(2 * (kp & 63))) ^ sw)) = h;
    }
}

// ---------------- persistent bf16-HMMA reservoir (3-slot ring, distributed producer) ---
// smem: slots 3x(A16K+B16K)=96K | v f32 stride 132 | ext f32 stride 129 | full mbar[3]
//       | stage counters[16].  Spike staging reuses [0, 64K) during epilogue.
#define SMO_V    98304
#define SMO_E    165888
#define SMO_MBAR 231936
#define SMO_CNT  231960
#define SM_DYN   232064

__global__ void __launch_bounds__(NTHR, 1)
k_persist(float* __restrict__ dout, float decayI) {
    extern __shared__ __align__(16) char sm[];
    float*    sv   = (float*)(sm + SMO_V);    // stride 132
    float*    se   = (float*)(sm + SMO_E);    // stride 129
    unsigned* scnt = (unsigned*)(sm + SMO_CNT);

    const int m   = blockIdx.z;
    const int bm0 = blockIdx.y * 128;
    const int bn0 = blockIdx.x * 128;
    const int tid  = threadIdx.x;
    const int lane = tid & 31, warp = tid >> 5;
    const int wm = warp >> 2, wn = warp & 3;      // 4x4 warps, warp tile 32x32

    // stage ownership for bulk spike stores
    const int bq      = bn0 >> 7;
    const int ownCnt  = (bq == 3) ? 3 : 2;
    const int st0     = (bq == 3) ? 6 : 2 * bq;
    const int prevCnt = (bq == 3) ? 1 : 2;
    const int pst0    = 9 + 2 * bq;

    unsigned smb   = (unsigned)__cvta_generic_to_shared(sm);
    unsigned mbarb = smb + SMO_MBAR;              // full barriers: +0, +8, +16

    if (tid == 0) {
        #pragma unroll
        for (int s = 0; s < 3; ++s)
            asm volatile("mbarrier.init.shared.b64 [%0], 1;" :: "r"(mbarb + 8u * s) : "memory");
    }
    __syncthreads();

    // -------- load ext tile into smem ONCE, coalesced --------
    for (int i = tid; i < 128 * 128; i += NTHR) {
        int r = i >> 7, c = i & 127;
        se[r * 129 + c] = g_ext[m][bm0 + r][bn0 + c];
    }
    __syncthreads();

    // -------- tick 0: v = 0 + ext --------
    for (int i = tid; i < 128 * 128; i += NTHR) {
        int r = i >> 7, c = i & 127;
        float cc   = se[r * 129 + c];
        float vnew = __fadd_rn(0.0f, cc);
        float u    = __fadd_rn(vnew, -1.0f);
        bool  sp   = (u >= 0.0f);
        sv[r * 132 + c] = sp ? 0.0f : vnew;
        write_spike0(m, bm0 + r, bn0 + c, sp);
    }

    // spike-count accumulator in registers (thread-owned elements)
    unsigned pack[8];
    #pragma unroll
    for (int q = 0; q < 8; ++q) pack[q] = 0u;
    #pragma unroll
    for (int im = 0; im < 2; ++im)
        #pragma unroll
        for (int in = 0; in < 4; ++in)
            #pragma unroll
            for (int f = 0; f < 4; ++f) {
                int r = wm * 32 + im * 16 + (lane >> 2) + (f >> 1) * 8;
                int c = wn * 32 + in * 8 + (lane & 3) * 2 + (f & 1);
                float vnew = __fadd_rn(0.0f, se[r * 129 + c]);
                float u    = __fadd_rn(vnew, -1.0f);
                int idx = im * 16 + in * 4 + f;
                if (u >= 0.0f) pack[idx >> 2] += (1u << (8 * (idx & 3)));
            }
    if (tid < NS) scnt[tid] = 0u;
    grid_barrier(1);

    const int r15   = lane & 15;
    const int kh16  = (lane >> 4) * 16;
    const unsigned swl = (((unsigned)r15 & 7u) << 4);

    unsigned fful = 0;                 // consumer full-parity bits per slot

    for (int t = 1; t < 16; ++t) {
        const int rbuf = (t - 1) & 1, wbuf = t & 1;

        // tick-start: slots provably free (grid barrier passed) — issue stages 0..2
        if (tid == 0) {
            asm volatile("fence.proxy.async;" ::: "memory");
            #pragma unroll
            for (int s = 0; s < 3; ++s) {
                unsigned mb = mbarb + 8u * s;
                unsigned sbase = smb + (unsigned)s * 32768u;
                mbar_expect(mb, 2u * SLOT);
                bulk_ld(sbase,        &g_Abuf[rbuf][m][s][bm0][0], SLOT, mb);
                bulk_ld(sbase + SLOT, &g_Wbig[m][s][bn0][0],       SLOT, mb);
            }
        }

        float c0[2][4][4], c1[2][4][4];
        #pragma unroll
        for (int a = 0; a < 2; ++a)
            #pragma unroll
            for (int b = 0; b < 4; ++b)
                #pragma unroll
                for (int f = 0; f < 4; ++f) { c0[a][b][f] = 0.f; c1[a][b][f] = 0.f; }

        for (int s = 0; s < NS; ++s) {
            int slot = s % 3;
            mbar_wait(mbarb + 8u * slot, (fful >> slot) & 1u);
            fful ^= (1u << slot);

            bool own = (s < OWN_STG);
            unsigned abase = smb + (unsigned)slot * 32768u;
            unsigned bbase = abase + SLOT;
            #pragma unroll
            for (int kk = 0; kk < 4; ++kk) {
                unsigned a[2][4], bfr[2][4];
                unsigned coff = ((unsigned)(kk * 32 + kh16)) ^ swl;
                #pragma unroll
                for (int im = 0; im < 2; ++im)
                    ldm4(a[im], abase + (unsigned)((wm * 32 + im * 16 + r15) * 128) + coff);
                #pragma unroll
                for (int ib = 0; ib < 2; ++ib)
                    ldm4(bfr[ib], bbase + (unsigned)((wn * 32 + ib * 16 + r15) * 128) + coff);
                if (own) {
                    #pragma unroll
                    for (int im = 0; im < 2; ++im)
                        #pragma unroll
                        for (int in = 0; in < 4; ++in) {
                            int ib = in >> 1, sub = in & 1;
                            mma16816(c0[im][in], a[im], bfr[ib][sub], bfr[ib][sub + 2]);
                        }
                } else {
                    #pragma unroll
                    for (int im = 0; im < 2; ++im)
                        #pragma unroll
                        for (int in = 0; in < 4; ++in) {
                            int ib = in >> 1, sub = in & 1;
                            mma16816(c1[im][in], a[im], bfr[ib][sub], bfr[ib][sub + 2]);
                        }
                }
            }
            // distributed producer: the LAST warp done with stage s issues stage s+3
            if (lane == 0) {
                unsigned old = atomicAdd(&scnt[s], 1u);
                if (old == 15u && s + 3 < NS) {
                    int s2 = s + 3, sl2 = s2 % 3;
                    unsigned mb = mbarb + 8u * sl2;
                    unsigned sbase = smb + (unsigned)sl2 * 32768u;
                    mbar_expect(mb, 2u * SLOT);
                    bulk_ld(sbase,        &g_Abuf[rbuf][m][s2][bm0][0], SLOT, mb);
                    bulk_ld(sbase + SLOT, &g_Wbig[m][s2][bn0][0],       SLOT, mb);
                }
            }
        }
        __syncthreads();                 // all warps done; slots become staging

        // -------- zero staging image (64 KB over slot region) --------
        {
            uint4 z; z.x = z.y = z.z = z.w = 0u;
            uint4* p = (uint4*)sm;
            for (int i = tid; i < 4096; i += NTHR) p[i] = z;
        }
        __syncthreads();

        // -------- epilogue: LIF (bitwise chain) + staged spike writes --------
        #pragma unroll
        for (int im = 0; im < 2; ++im)
            #pragma unroll
            for (int in = 0; in < 4; ++in)
                #pragma unroll
                for (int f = 0; f < 4; ++f) {
                    int r = wm * 32 + im * 16 + (lane >> 2) + (f >> 1) * 8;
                    int c = wn * 32 + in * 8 + (lane & 3) * 2 + (f & 1);
                    int gc = bn0 + c;
                    int ci = (int)c0[im][in][f];
                    int rr = ci & 8191;
                    int aEi = (rr < 4096) ? rr : rr - 8192;
                    int aIi = (ci - aEi) >> 13;
                    float ext  = se[r * 129 + c];
                    float t1   = __fadd_rn(ext, c1[im][in][f]);
                    float t2   = __fadd_rn(t1, (float)aEi);
                    float cur  = __fadd_rn(t2, (float)aIi);
                    float vold = sv[r * 132 + c];
                    float dec  = (gc < NEx) ? 0.5f : decayI;
                    float vnew = __fadd_rn(__fmul_rn(vold, dec), cur);
                    float u    = __fadd_rn(vnew, -1.0f);
                    bool  sp   = (u >= 0.0f);
                    sv[r * 132 + c] = sp ? 0.0f : vnew;
                    int idx = im * 16 + in * 4 + f;
                    if (sp) pack[idx >> 2] += (1u << (8 * (idx & 3)));
                    unsigned short h = sp ? 0x3F80 : 0;
                    unsigned swr = (((unsigned)r & 7u) << 4);
                    int kown = (gc < NEx) ? gc : (gc + (K_ISEC - NEx));
                    unsigned soff = (unsigned)(((kown >> 6) - st0) * 16384 + r * 128)
                                    + (((unsigned)(2 * (kown & 63))) ^ swr);
                    *(unsigned short*)(sm + soff) = h;
                    if (gc < NEx) {
                        int kp = K_PSEC + gc;
                        unsigned poff = (unsigned)((ownCnt + ((kp >> 6) - pst0)) * 16384
                                                   + r * 128)
                                        + (((unsigned)(2 * (kp & 63))) ^ swr);
                        *(unsigned short*)(sm + poff) = h;
                    }
                }
        __syncthreads();

        // -------- 4 bulk stores: staging -> g_Abuf[wbuf] --------
        if (tid == 0) {
            asm volatile("fence.proxy.async.shared::cta;" ::: "memory");
            for (int j = 0; j < ownCnt; ++j)
                bulk_st(&g_Abuf[wbuf][m][st0 + j][bm0][0], smb + (unsigned)(j * 16384));
            for (int j = 0; j < prevCnt; ++j)
                bulk_st(&g_Abuf[wbuf][(m + 1) & 7][pst0 + j][bm0][0],
                        smb + (unsigned)((ownCnt + j) * 16384));
            asm volatile("cp.async.bulk.commit_group;" ::: "memory");
            asm volatile("cp.async.bulk.wait_group 0;" ::: "memory");
        }

        if (t < 15) {
            if (tid < NS) scnt[tid] = 0u;       // reset stage counters for next tick
            grid_barrier((unsigned)(t + 1));    // syncthreads inside publishes the reset
        }
    }

    // -------- final: write spike counts from registers --------
    #pragma unroll
    for (int im = 0; im < 2; ++im)
        #pragma unroll
        for (int in = 0; in < 4; ++in)
            #pragma unroll
            for (int f = 0; f < 4; ++f) {
                int r = wm * 32 + im * 16 + (lane >> 2) + (f >> 1) * 8;
                int c = wn * 32 + in * 8 + (lane & 3) * 2 + (f & 1);
                int idx = im * 16 + in * 4 + f;
                unsigned cnt = (pack[idx >> 2] >> (8 * (idx & 3))) & 255u;
                dout[(long long)(bm0 + r) * (MESH * NN) + m * NN + bn0 + c] = (float)cnt;
            }
}

// ---------------- launch ----------------
extern "C" void kernel_launch(void* const* d_in, const int* in_sizes, int n_in,
                              void* d_out, int out_size) {
    const float* x       = (const float*)d_in[0];
    const float* W_in    = (const float*)d_in[1];
    const float* b_in    = (const float*)d_in[2];
    const float* W_inter = (const float*)d_in[3];
    const float* W_EE    = (const float*)d_in[4];
    const float* W_EI    = (const float*)d_in[5];
    const float* W_IE    = (const float*)d_in[6];
    const float* W_II    = (const float*)d_in[7];
    float* out = (float*)d_out;
    const float decayI = (float)(1.0 - 1.0 / 1.5);

    cudaFuncSetAttribute(k_persist, cudaFuncAttributeMaxDynamicSharedMemorySize, SM_DYN);

    // local launch idx 3 == k_persist (ncu capture slot)
    k_init<<<2048, 256>>>(W_in, W_inter, W_EE, W_EI, W_IE, W_II);   // 0
    k_ext<<<dim3(BB / EXT_BT, MESH), 512>>>(x, b_in);               // 1
    k_dummy<<<1, 1>>>();                                            // 2
    dim3 grid(4, 4, 8);                                             // 128 CTAs, 1/SM
    k_persist<<<grid, NTHR, SM_DYN>>>(out, decayI);                 // 3
}

// round 16
// speedup vs baseline: 1.3257x; 1.0357x over previous
#include <cuda_runtime.h>
#include <cuda_bf16.h>

#define MESH 8
#define NN   512
#define NEx  409
#define NIx  103
#define DD   243
#define BB   512
// K layout (repacked, zero own-pad): [0,409) own E, [409,512) own I (weights x8192),
// [512,921) prev-mesh E, [921,960) pad. 15 stages of 64. Stages 0..7 -> c0, 8..14 -> c1.
#define KT      960
#define K_IOFF  409
#define K_POFF  512
#define ISCALE  8192.0f
#define NS      15
#define OWN_STG 8
#define NTHR    512
#define SLOT    16384u

// ---------------- device state (stage-major, SW128-swizzled 128B rows) ----------------
__device__ __align__(16) __nv_bfloat16 g_Wbig[MESH][NS][NN][64];
__device__ __align__(16) __nv_bfloat16 g_Abuf[2][MESH][NS][BB][64];
__device__ float g_WinT[MESH][DD][NN];
__device__ float g_ext[MESH][BB][NN];
__device__ unsigned g_barp[MESH][4];    // per-(mesh, batch-tile) barrier counters

__device__ __forceinline__ float quantw(float w) {
    float q = rintf(w);                  // round-half-even == jnp.round
    return fminf(7.f, fmaxf(-8.f, q));
}

// ---------------- combined init (zero + Wbig + WinT), vectorized ----------------
__global__ void k_init(const float* __restrict__ W_in, const float* __restrict__ W_inter,
                       const float* __restrict__ W_EE, const float* __restrict__ W_EI,
                       const float* __restrict__ W_IE, const float* __restrict__ W_II) {
    long long stride = (long long)gridDim.x * blockDim.x;
    long long i0 = (long long)blockIdx.x * blockDim.x + threadIdx.x;
    if (i0 < MESH * 4) g_barp[i0 >> 2][i0 & 3] = 0u;

    // zero spike buffers with 16B stores
    uint4 z; z.x = z.y = z.z = z.w = 0u;
    uint4* A4 = (uint4*)&g_Abuf[0][0][0][0][0];
    long long nA4 = 2LL * MESH * NS * BB * 64 * 2 / 16;
    for (long long i = i0; i < nA4; i += stride) A4[i] = z;

    // Wbig: 8 consecutive k per 16B store (swizzle is 16B-granular)
    long long totW = (long long)MESH * NN * (KT / 8);
    for (long long idx = i0; idx < totW; idx += stride) {
        int kg = (int)(idx % (KT / 8));
        int n  = (int)((idx / (KT / 8)) % NN);
        int m  = (int)(idx / ((long long)(KT / 8) * NN));
        int k0 = kg * 8;
        __nv_bfloat16 buf8[8];
        #pragma unroll
        for (int j = 0; j < 8; ++j) {
            int k = k0 + j;
            float w = 0.f;
            if (k < K_IOFF) {                        // own E: W_EE / W_EI
                w = (n < NEx) ? W_EE[((long long)m * NEx + n) * NEx + k]
                              : W_EI[((long long)m * NIx + (n - NEx)) * NEx + k];
                w = quantw(w);
            } else if (k < K_POFF) {                 // own I, packed *8192 (exact in bf16)
                int ki = k - K_IOFF;
                w = (n < NEx) ? W_IE[((long long)m * NEx + n) * NIx + ki]
                              : W_II[((long long)m * NIx + (n - NEx)) * NIx + ki];
                w = quantw(w) * ISCALE;
            } else {                                 // inter: mesh m receives W_inter[m-1]
                int kp = k - K_POFF;
                if (kp < NEx) {
                    int mp = (m + MESH - 1) % MESH;
                    w = W_inter[((long long)mp * NN + n) * NEx + kp];
                }
                w = quantw(w);
            }
            buf8[j] = __float2bfloat16(w);
        }
        int st = k0 >> 6, kk = k0 & 63;
        unsigned off = ((unsigned)(2 * kk)) ^ (((unsigned)n & 7u) << 4);
        *(uint4*)((char*)&g_Wbig[m][st][n][0] + off) = *(uint4*)buf8;
    }

    long long totI = (long long)MESH * NN * DD;
    for (long long idx = i0; idx < totI; idx += stride) {
        int d = (int)(idx % DD);
        int n = (int)((idx / DD) % NN);
        int m = (int)(idx / ((long long)DD * NN));
        g_WinT[m][d][n] = quantw(W_in[idx]);
    }
}

// ---------------- ext_proj: f32x2 packed serial-d FMA (per-half bitwise == scalar) ------
#define EXT_BT 16
__device__ __forceinline__ unsigned long long fma2(unsigned long long a, unsigned long long b,
                                                   unsigned long long c) {
    unsigned long long d;
    asm("fma.rn.f32x2 %0, %1, %2, %3;" : "=l"(d) : "l"(a), "l"(b), "l"(c));
    return d;
}
__global__ void __launch_bounds__(512)
k_ext(const float* __restrict__ X, const float* __restrict__ b_in) {
    __shared__ __align__(16) float sx[DD][EXT_BT];
    const int m  = blockIdx.y;
    const int b0 = blockIdx.x * EXT_BT;
    const int n  = threadIdx.x;
    for (int i = threadIdx.x; i < EXT_BT * DD; i += 512) {
        int bb = i / DD, d = i % DD;
        sx[d][bb] = X[(long long)(b0 + bb) * DD + d];
    }
    __syncthreads();
    unsigned long long acc2[8];
    #pragma unroll
    for (int q = 0; q < 8; ++q) acc2[q] = 0ull;
    for (int d = 0; d < DD; ++d) {
        float w = g_WinT[m][d][n];
        unsigned long long w2;
        asm("mov.b64 %0, {%1,%1};" : "=l"(w2) : "r"(__float_as_uint(w)));
        const unsigned long long* p = reinterpret_cast<const unsigned long long*>(&sx[d][0]);
        #pragma unroll
        for (int q = 0; q < 8; ++q) acc2[q] = fma2(p[q], w2, acc2[q]);
    }
    float bi = b_in[m * NN + n];
    #pragma unroll
    for (int q = 0; q < 8; ++q) {
        unsigned lo, hi;
        asm("mov.b64 {%0,%1}, %2;" : "=r"(lo), "=r"(hi) : "l"(acc2[q]));
        g_ext[m][b0 + 2 * q][n]     = __fadd_rn(__uint_as_float(lo), bi);
        g_ext[m][b0 + 2 * q + 1][n] = __fadd_rn(__uint_as_float(hi), bi);
    }
}

__global__ void k_dummy() {}

// ---------------- asm helpers ----------------
__device__ __forceinline__ void ldm4(unsigned* r, unsigned addr) {
    asm volatile("ldmatrix.sync.aligned.m8n8.x4.shared.b16 {%0,%1,%2,%3}, [%4];\n"
                 : "=r"(r[0]), "=r"(r[1]), "=r"(r[2]), "=r"(r[3]) : "r"(addr));
}
__device__ __forceinline__ void mma16816(float* c, const unsigned* a, unsigned b0, unsigned b1) {
    asm volatile("mma.sync.aligned.m16n8k16.row.col.f32.bf16.bf16.f32 "
                 "{%0,%1,%2,%3}, {%4,%5,%6,%7}, {%8,%9}, {%0,%1,%2,%3};\n"
                 : "+f"(c[0]), "+f"(c[1]), "+f"(c[2]), "+f"(c[3])
                 : "r"(a[0]), "r"(a[1]), "r"(a[2]), "r"(a[3]), "r"(b0), "r"(b1));
}
__device__ __forceinline__ void bulk_ld(unsigned dst, const void* src, unsigned bytes,
                                        unsigned mbar) {
    asm volatile("cp.async.bulk.shared::cluster.global.mbarrier::complete_tx::bytes "
                 "[%0], [%1], %2, [%3];"
                 :: "r"(dst), "l"(src), "r"(bytes), "r"(mbar) : "memory");
}
__device__ __forceinline__ void bulk_st(void* gdst, unsigned ssrc) {
    asm volatile("cp.async.bulk.global.shared::cta.bulk_group [%0], [%1], %2;"
                 :: "l"(gdst), "r"(ssrc), "r"(SLOT) : "memory");
}
__device__ __forceinline__ void mbar_expect(unsigned mbar, unsigned bytes) {
    asm volatile("mbarrier.arrive.expect_tx.shared.b64 _, [%0], %1;"
                 :: "r"(mbar), "r"(bytes) : "memory");
}
__device__ __forceinline__ void mbar_wait(unsigned addr, unsigned parity) {
    unsigned done;
    do {
        asm volatile(
            "{\n\t.reg .pred p;\n\t"
            "mbarrier.try_wait.parity.shared.b64 p, [%1], %2, 0x989680;\n\t"
            "selp.b32 %0, 1, 0, p;\n\t}"
            : "=r"(done) : "r"(addr), "r"(parity) : "memory");
    } while (!done);
}

// per-(mesh,batch-tile) group barrier: 8 arrivals per group per tick
__device__ __forceinline__ void grid_barrier(unsigned phase, int m, int bt) {
    __threadfence();
    __syncthreads();
    if (threadIdx.x == 0) {
        asm volatile("red.release.gpu.global.add.u32 [%0], %1;"
                     :: "l"(&g_barp[m][bt]), "r"(1u) : "memory");
        asm volatile("red.release.gpu.global.add.u32 [%0], %1;"
                     :: "l"(&g_barp[(m + 1) & 7][bt]), "r"(1u) : "memory");
        unsigned target = phase * 8u, v;
        do {
            asm volatile("ld.acquire.gpu.global.u32 %0, [%1];"
                         : "=r"(v) : "l"(&g_barp[m][bt]) : "memory");
            if (v < target) __nanosleep(64);
        } while (v < target);
    }
    __syncthreads();
}

// scattered spike write (tick 0 only); kown = gc uniformly, prev at 512+gc
__device__ __forceinline__ void write_spike0(int m, int grow, int gc, bool sp) {
    unsigned short h = sp ? 0x3F80 : 0;
    unsigned sw = (((unsigned)grow & 7u) << 4);
    *(unsigned short*)((char*)&g_Abuf[0][m][gc >> 6][grow][0]
                       + (((unsigned)(2 * (gc & 63))) ^ sw)) = h;
    if (gc < NEx) {
        int kp = K_POFF + gc;
        *(unsigned short*)((char*)&g_Abuf[0][(m + 1) & 7][kp >> 6][grow][0]
                           + (((unsigned)(2 * (kp & 63))) ^ sw)) = h;
    }
}

// ---------------- persistent bf16-HMMA reservoir (repacked K, group barriers) ----------
// smem: slots 3x(A16K+B16K)=96K | v f32 stride 132 | ext f32 stride 129 | full mbar[3]
//       | stage counters[15].  Spike staging reuses [0, 64K) during epilogue:
//       chunks 0,1 = own stages 2bq,2bq+1 ; chunks 2,3 = prev stages 8+2bq,8+2bq+1.
#define SMO_V    98304
#define SMO_E    165888
#define SMO_MBAR 231936
#define SMO_CNT  231960
#define SM_DYN   232064

__global__ void __launch_bounds__(NTHR, 1)
k_persist(float* __restrict__ dout, float decayI) {
    extern __shared__ __align__(16) char sm[];
    float*    sv   = (float*)(sm + SMO_V);    // stride 132
    float*    se   = (float*)(sm + SMO_E);    // stride 129
    unsigned* scnt = (unsigned*)(sm + SMO_CNT);

    const int m   = blockIdx.z;
    const int bt  = blockIdx.y;
    const int bm0 = bt * 128;
    const int bn0 = blockIdx.x * 128;
    const int tid  = threadIdx.x;
    const int lane = tid & 31, warp = tid >> 5;
    const int wm = warp >> 2, wn = warp & 3;      // 4x4 warps, warp tile 32x32

    const int bq      = bn0 >> 7;                 // 0..3
    const int st0     = 2 * bq;                   // own chunk stages
    const int pst0    = 8 + 2 * bq;               // prev chunk stages
    const int prevCnt = (bq == 3) ? 1 : 2;

    unsigned smb   = (unsigned)__cvta_generic_to_shared(sm);
    unsigned mbarb = smb + SMO_MBAR;              // full barriers: +0, +8, +16

    if (tid == 0) {
        #pragma unroll
        for (int s = 0; s < 3; ++s)
            asm volatile("mbarrier.init.shared.b64 [%0], 1;" :: "r"(mbarb + 8u * s) : "memory");
    }
    __syncthreads();

    // -------- load ext tile into smem ONCE, coalesced --------
    for (int i = tid; i < 128 * 128; i += NTHR) {
        int r = i >> 7, c = i & 127;
        se[r * 129 + c] = g_ext[m][bm0 + r][bn0 + c];
    }
    __syncthreads();

    // -------- tick 0: v = 0 + ext --------
    for (int i = tid; i < 128 * 128; i += NTHR) {
        int r = i >> 7, c = i & 127;
        float cc   = se[r * 129 + c];
        float vnew = __fadd_rn(0.0f, cc);
        float u    = __fadd_rn(vnew, -1.0f);
        bool  sp   = (u >= 0.0f);
        sv[r * 132 + c] = sp ? 0.0f : vnew;
        write_spike0(m, bm0 + r, bn0 + c, sp);
    }

    // spike-count accumulator in registers (thread-owned elements)
    unsigned pack[8];
    #pragma unroll
    for (int q = 0; q < 8; ++q) pack[q] = 0u;
    #pragma unroll
    for (int im = 0; im < 2; ++im)
        #pragma unroll
        for (int in = 0; in < 4; ++in)
            #pragma unroll
            for (int f = 0; f < 4; ++f) {
                int r = wm * 32 + im * 16 + (lane >> 2) + (f >> 1) * 8;
                int c = wn * 32 + in * 8 + (lane & 3) * 2 + (f & 1);
                float vnew = __fadd_rn(0.0f, se[r * 129 + c]);
                float u    = __fadd_rn(vnew, -1.0f);
                int idx = im * 16 + in * 4 + f;
                if (u >= 0.0f) pack[idx >> 2] += (1u << (8 * (idx & 3)));
            }
    if (tid < NS) scnt[tid] = 0u;
    grid_barrier(1, m, bt);

    const int r15   = lane & 15;
    const int kh16  = (lane >> 4) * 16;
    const unsigned swl = (((unsigned)r15 & 7u) << 4);

    unsigned fful = 0;                 // consumer full-parity bits per slot

    for (int t = 1; t < 16; ++t) {
        const int rbuf = (t - 1) & 1, wbuf = t & 1;

        // tick-start: slots provably free (group barrier passed) — issue stages 0..2
        if (tid == 0) {
            asm volatile("fence.proxy.async;" ::: "memory");
            #pragma unroll
            for (int s = 0; s < 3; ++s) {
                unsigned mb = mbarb + 8u * s;
                unsigned sbase = smb + (unsigned)s * 32768u;
                mbar_expect(mb, 2u * SLOT);
                bulk_ld(sbase,        &g_Abuf[rbuf][m][s][bm0][0], SLOT, mb);
                bulk_ld(sbase + SLOT, &g_Wbig[m][s][bn0][0],       SLOT, mb);
            }
        }

        float c0[2][4][4], c1[2][4][4];
        #pragma unroll
        for (int a = 0; a < 2; ++a)
            #pragma unroll
            for (int b = 0; b < 4; ++b)
                #pragma unroll
                for (int f = 0; f < 4; ++f) { c0[a][b][f] = 0.f; c1[a][b][f] = 0.f; }

        for (int s = 0; s < NS; ++s) {
            int slot = s % 3;
            mbar_wait(mbarb + 8u * slot, (fful >> slot) & 1u);
            fful ^= (1u << slot);

            bool own = (s < OWN_STG);
            unsigned abase = smb + (unsigned)slot * 32768u;
            unsigned bbase = abase + SLOT;
            #pragma unroll
            for (int kk = 0; kk < 4; ++kk) {
                unsigned a[2][4], bfr[2][4];
                unsigned coff = ((unsigned)(kk * 32 + kh16)) ^ swl;
                #pragma unroll
                for (int im = 0; im < 2; ++im)
                    ldm4(a[im], abase + (unsigned)((wm * 32 + im * 16 + r15) * 128) + coff);
                #pragma unroll
                for (int ib = 0; ib < 2; ++ib)
                    ldm4(bfr[ib], bbase + (unsigned)((wn * 32 + ib * 16 + r15) * 128) + coff);
                if (own) {
                    #pragma unroll
                    for (int im = 0; im < 2; ++im)
                        #pragma unroll
                        for (int in = 0; in < 4; ++in) {
                            int ib = in >> 1, sub = in & 1;
                            mma16816(c0[im][in], a[im], bfr[ib][sub], bfr[ib][sub + 2]);
                        }
                } else {
                    #pragma unroll
                    for (int im = 0; im < 2; ++im)
                        #pragma unroll
                        for (int in = 0; in < 4; ++in) {
                            int ib = in >> 1, sub = in & 1;
                            mma16816(c1[im][in], a[im], bfr[ib][sub], bfr[ib][sub + 2]);
                        }
                }
            }
            // distributed producer: the LAST warp done with stage s issues stage s+3
            if (lane == 0) {
                unsigned old = atomicAdd(&scnt[s], 1u);
                if (old == 15u && s + 3 < NS) {
                    int s2 = s + 3, sl2 = s2 % 3;
                    unsigned mb = mbarb + 8u * sl2;
                    unsigned sbase = smb + (unsigned)sl2 * 32768u;
                    mbar_expect(mb, 2u * SLOT);
                    bulk_ld(sbase,        &g_Abuf[rbuf][m][s2][bm0][0], SLOT, mb);
                    bulk_ld(sbase + SLOT, &g_Wbig[m][s2][bn0][0],       SLOT, mb);
                }
            }
        }
        __syncthreads();                 // all warps done; slots become staging

        // -------- zero only the padded prev chunk (bq==3, chunk idx 2) --------
        if (bq == 3) {
            uint4 z; z.x = z.y = z.z = z.w = 0u;
            uint4* p = (uint4*)(sm + 2 * 16384);
            for (int i = tid; i < 1024; i += NTHR) p[i] = z;
            __syncthreads();
        }

        // -------- epilogue: LIF (bitwise chain) + staged spike writes --------
        #pragma unroll
        for (int im = 0; im < 2; ++im)
            #pragma unroll
            for (int in = 0; in < 4; ++in)
                #pragma unroll
                for (int f = 0; f < 4; ++f) {
                    int r = wm * 32 + im * 16 + (lane >> 2) + (f >> 1) * 8;
                    int c = wn * 32 + in * 8 + (lane & 3) * 2 + (f & 1);
                    int gc = bn0 + c;
                    int ci = (int)c0[im][in][f];
                    int rr = ci & 8191;
                    int aEi = (rr < 4096) ? rr : rr - 8192;
                    int aIi = (ci - aEi) >> 13;
                    float ext  = se[r * 129 + c];
                    float t1   = __fadd_rn(ext, c1[im][in][f]);
                    float t2   = __fadd_rn(t1, (float)aEi);
                    float cur  = __fadd_rn(t2, (float)aIi);
                    float vold = sv[r * 132 + c];
                    float dec  = (gc < NEx) ? 0.5f : decayI;
                    float vnew = __fadd_rn(__fmul_rn(vold, dec), cur);
                    float u    = __fadd_rn(vnew, -1.0f);
                    bool  sp   = (u >= 0.0f);
                    sv[r * 132 + c] = sp ? 0.0f : vnew;
                    int idx = im * 16 + in * 4 + f;
                    if (sp) pack[idx >> 2] += (1u << (8 * (idx & 3)));
                    unsigned short h = sp ? 0x3F80 : 0;
                    unsigned swr = (((unsigned)r & 7u) << 4);
                    // own staging: chunk (c>>6), prev = own + 32768 (same k&63, same row)
                    unsigned soff = (unsigned)((c >> 6) * 16384 + r * 128)
                                    + (((unsigned)(2 * (gc & 63))) ^ swr);
                    *(unsigned short*)(sm + soff) = h;
                    if (gc < NEx)
                        *(unsigned short*)(sm + soff + 32768) = h;
                }
        __syncthreads();

        // -------- bulk stores: staging -> g_Abuf[wbuf] --------
        if (tid == 0) {
            asm volatile("fence.proxy.async.shared::cta;" ::: "memory");
            #pragma unroll
            for (int j = 0; j < 2; ++j)
                bulk_st(&g_Abuf[wbuf][m][st0 + j][bm0][0], smb + (unsigned)(j * 16384));
            for (int j = 0; j < prevCnt; ++j)
                bulk_st(&g_Abuf[wbuf][(m + 1) & 7][pst0 + j][bm0][0],
                        smb + (unsigned)((2 + j) * 16384));
            asm volatile("cp.async.bulk.commit_group;" ::: "memory");
            asm volatile("cp.async.bulk.wait_group 0;" ::: "memory");
        }

        if (t < 15) {
            if (tid < NS) scnt[tid] = 0u;             // reset stage counters
            grid_barrier((unsigned)(t + 1), m, bt);   // syncthreads publishes the reset
        }
    }

    // -------- final: write spike counts from registers --------
    #pragma unroll
    for (int im = 0; im < 2; ++im)
        #pragma unroll
        for (int in = 0; in < 4; ++in)
            #pragma unroll
            for (int f = 0; f < 4; ++f) {
                int r = wm * 32 + im * 16 + (lane >> 2) + (f >> 1) * 8;
                int c = wn * 32 + in * 8 + (lane & 3) * 2 + (f & 1);
                int idx = im * 16 + in * 4 + f;
                unsigned cnt = (pack[idx >> 2] >> (8 * (idx & 3))) & 255u;
                dout[(long long)(bm0 + r) * (MESH * NN) + m * NN + bn0 + c] = (float)cnt;
            }
}

// ---------------- launch ----------------
extern "C" void kernel_launch(void* const* d_in, const int* in_sizes, int n_in,
                              void* d_out, int out_size) {
    const float* x       = (const float*)d_in[0];
    const float* W_in    = (const float*)d_in[1];
    const float* b_in    = (const float*)d_in[2];
    const float* W_inter = (const float*)d_in[3];
    const float* W_EE    = (const float*)d_in[4];
    const float* W_EI    = (const float*)d_in[5];
    const float* W_IE    = (const float*)d_in[6];
    const float* W_II    = (const float*)d_in[7];
    float* out = (float*)d_out;
    const float decayI = (float)(1.0 - 1.0 / 1.5);

    cudaFuncSetAttribute(k_persist, cudaFuncAttributeMaxDynamicSharedMemorySize, SM_DYN);

    // local launch idx 3 == k_persist (ncu capture slot)
    k_init<<<2048, 256>>>(W_in, W_inter, W_EE, W_EI, W_IE, W_II);   // 0
    k_ext<<<dim3(BB / EXT_BT, MESH), 512>>>(x, b_in);               // 1
    k_dummy<<<1, 1>>>();                                            // 2
    dim3 grid(4, 4, 8);                                             // 128 CTAs, 1/SM
    k_persist<<<grid, NTHR, SM_DYN>>>(out, decayI);                 // 3
}

// round 17
// speedup vs baseline: 1.3372x; 1.0086x over previous
#include <cuda_runtime.h>
#include <cuda_bf16.h>

#define MESH 8
#define NN   512
#define NEx  409
#define NIx  103
#define DD   243
#define BB   512
// K layout (zero own-pad): [0,409) own E, [409,512) own I (weights x8192),
// [512,921) prev-mesh E, [921,960) pad. 15 stages of 64. Stages 0..7 -> c0, 8..14 -> c1.
#define KT      960
#define K_IOFF  409
#define K_POFF  512
#define ISCALE  8192.0f
#define NS      15
#define OWN_STG 8
#define NTHR    512
#define SLOT    16384u

// ---------------- device state (stage-major, SW128-swizzled 128B rows) ----------------
__device__ __align__(16) __nv_bfloat16 g_Wbig[MESH][NS][NN][64];
__device__ __align__(16) __nv_bfloat16 g_Abuf[2][MESH][NS][BB][64];
__device__ float g_WinT[MESH][DD][NN];
__device__ float g_ext[MESH][BB][NN];
__device__ float4 g_extp[MESH][4][4][8][NTHR];   // [m][bt][nq][q][tid] thread-owned ext
__device__ unsigned g_barp[MESH][4];             // per-(mesh, batch-tile) barrier counters

__device__ __forceinline__ float quantw(float w) {
    float q = rintf(w);                  // round-half-even == jnp.round
    return fminf(7.f, fmaxf(-8.f, q));
}

// ---------------- combined init (zero + Wbig + WinT), vectorized ----------------
__global__ void k_init(const float* __restrict__ W_in, const float* __restrict__ W_inter,
                       const float* __restrict__ W_EE, const float* __restrict__ W_EI,
                       const float* __restrict__ W_IE, const float* __restrict__ W_II) {
    long long stride = (long long)gridDim.x * blockDim.x;
    long long i0 = (long long)blockIdx.x * blockDim.x + threadIdx.x;
    if (i0 < MESH * 4) g_barp[i0 >> 2][i0 & 3] = 0u;

    uint4 z; z.x = z.y = z.z = z.w = 0u;
    uint4* A4 = (uint4*)&g_Abuf[0][0][0][0][0];
    long long nA4 = 2LL * MESH * NS * BB * 64 * 2 / 16;
    for (long long i = i0; i < nA4; i += stride) A4[i] = z;

    long long totW = (long long)MESH * NN * (KT / 8);
    for (long long idx = i0; idx < totW; idx += stride) {
        int kg = (int)(idx % (KT / 8));
        int n  = (int)((idx / (KT / 8)) % NN);
        int m  = (int)(idx / ((long long)(KT / 8) * NN));
        int k0 = kg * 8;
        __nv_bfloat16 buf8[8];
        #pragma unroll
        for (int j = 0; j < 8; ++j) {
            int k = k0 + j;
            float w = 0.f;
            if (k < K_IOFF) {                        // own E: W_EE / W_EI
                w = (n < NEx) ? W_EE[((long long)m * NEx + n) * NEx + k]
                              : W_EI[((long long)m * NIx + (n - NEx)) * NEx + k];
                w = quantw(w);
            } else if (k < K_POFF) {                 // own I, packed *8192 (exact in bf16)
                int ki = k - K_IOFF;
                w = (n < NEx) ? W_IE[((long long)m * NEx + n) * NIx + ki]
                              : W_II[((long long)m * NIx + (n - NEx)) * NIx + ki];
                w = quantw(w) * ISCALE;
            } else {                                 // inter: mesh m receives W_inter[m-1]
                int kp = k - K_POFF;
                if (kp < NEx) {
                    int mp = (m + MESH - 1) % MESH;
                    w = W_inter[((long long)mp * NN + n) * NEx + kp];
                }
                w = quantw(w);
            }
            buf8[j] = __float2bfloat16(w);
        }
        int st = k0 >> 6, kk = k0 & 63;
        unsigned off = ((unsigned)(2 * kk)) ^ (((unsigned)n & 7u) << 4);
        *(uint4*)((char*)&g_Wbig[m][st][n][0] + off) = *(uint4*)buf8;
    }

    long long totI = (long long)MESH * NN * DD;
    for (long long idx = i0; idx < totI; idx += stride) {
        int d = (int)(idx % DD);
        int n = (int)((idx / DD) % NN);
        int m = (int)(idx / ((long long)DD * NN));
        g_WinT[m][d][n] = quantw(W_in[idx]);
    }
}

// ---------------- ext_proj: f32x2 packed serial-d FMA (per-half bitwise == scalar) ------
#define EXT_BT 16
__device__ __forceinline__ unsigned long long fma2(unsigned long long a, unsigned long long b,
                                                   unsigned long long c) {
    unsigned long long d;
    asm("fma.rn.f32x2 %0, %1, %2, %3;" : "=l"(d) : "l"(a), "l"(b), "l"(c));
    return d;
}
__global__ void __launch_bounds__(512)
k_ext(const float* __restrict__ X, const float* __restrict__ b_in) {
    __shared__ __align__(16) float sx[DD][EXT_BT];
    const int m  = blockIdx.y;
    const int b0 = blockIdx.x * EXT_BT;
    const int n  = threadIdx.x;
    for (int i = threadIdx.x; i < EXT_BT * DD; i += 512) {
        int bb = i / DD, d = i % DD;
        sx[d][bb] = X[(long long)(b0 + bb) * DD + d];
    }
    __syncthreads();
    unsigned long long acc2[8];
    #pragma unroll
    for (int q = 0; q < 8; ++q) acc2[q] = 0ull;
    for (int d = 0; d < DD; ++d) {
        float w = g_WinT[m][d][n];
        unsigned long long w2;
        asm("mov.b64 %0, {%1,%1};" : "=l"(w2) : "r"(__float_as_uint(w)));
        const unsigned long long* p = reinterpret_cast<const unsigned long long*>(&sx[d][0]);
        #pragma unroll
        for (int q = 0; q < 8; ++q) acc2[q] = fma2(p[q], w2, acc2[q]);
    }
    float bi = b_in[m * NN + n];
    #pragma unroll
    for (int q = 0; q < 8; ++q) {
        unsigned lo, hi;
        asm("mov.b64 {%0,%1}, %2;" : "=r"(lo), "=r"(hi) : "l"(acc2[q]));
        g_ext[m][b0 + 2 * q][n]     = __fadd_rn(__uint_as_float(lo), bi);
        g_ext[m][b0 + 2 * q + 1][n] = __fadd_rn(__uint_as_float(hi), bi);
    }
}

// ---------------- permute ext into thread-owned float4 layout (4x4 warp grid) ----------
__global__ void k_perm() {
    long long stride = (long long)gridDim.x * blockDim.x;
    long long tot = (long long)MESH * 4 * 4 * 8 * NTHR;
    for (long long g = (long long)blockIdx.x * blockDim.x + threadIdx.x; g < tot; g += stride) {
        int tid = (int)(g & 511);
        int q   = (int)((g >> 9) & 7);
        int nq  = (int)((g >> 12) & 3);
        int bt  = (int)((g >> 14) & 3);
        int m   = (int)(g >> 16);
        int im = q >> 2, in = q & 3;
        int warp = tid >> 5, lane = tid & 31;
        int wm = warp >> 2, wn = warp & 3;
        float4 v4;
        float* vp = &v4.x;
        #pragma unroll
        for (int f = 0; f < 4; ++f) {
            int r = wm * 32 + im * 16 + (lane >> 2) + (f >> 1) * 8;
            int c = wn * 32 + in * 8 + (lane & 3) * 2 + (f & 1);
            vp[f] = g_ext[m][bt * 128 + r][nq * 128 + c];
        }
        g_extp[m][bt][nq][q][tid] = v4;
    }
}

// ---------------- asm helpers ----------------
__device__ __forceinline__ void ldm4(unsigned* r, unsigned addr) {
    asm volatile("ldmatrix.sync.aligned.m8n8.x4.shared.b16 {%0,%1,%2,%3}, [%4];\n"
                 : "=r"(r[0]), "=r"(r[1]), "=r"(r[2]), "=r"(r[3]) : "r"(addr));
}
__device__ __forceinline__ void mma16816(float* c, const unsigned* a, unsigned b0, unsigned b1) {
    asm volatile("mma.sync.aligned.m16n8k16.row.col.f32.bf16.bf16.f32 "
                 "{%0,%1,%2,%3}, {%4,%5,%6,%7}, {%8,%9}, {%0,%1,%2,%3};\n"
                 : "+f"(c[0]), "+f"(c[1]), "+f"(c[2]), "+f"(c[3])
                 : "r"(a[0]), "r"(a[1]), "r"(a[2]), "r"(a[3]), "r"(b0), "r"(b1));
}
__device__ __forceinline__ void bulk_ld(unsigned dst, const void* src, unsigned bytes,
                                        unsigned mbar) {
    asm volatile("cp.async.bulk.shared::cluster.global.mbarrier::complete_tx::bytes "
                 "[%0], [%1], %2, [%3];"
                 :: "r"(dst), "l"(src), "r"(bytes), "r"(mbar) : "memory");
}
__device__ __forceinline__ void bulk_st(void* gdst, unsigned ssrc) {
    asm volatile("cp.async.bulk.global.shared::cta.bulk_group [%0], [%1], %2;"
                 :: "l"(gdst), "r"(ssrc), "r"(SLOT) : "memory");
}
__device__ __forceinline__ void mbar_expect(unsigned mbar, unsigned bytes) {
    asm volatile("mbarrier.arrive.expect_tx.shared.b64 _, [%0], %1;"
                 :: "r"(mbar), "r"(bytes) : "memory");
}
__device__ __forceinline__ void mbar_wait(unsigned addr, unsigned parity) {
    unsigned done;
    do {
        asm volatile(
            "{\n\t.reg .pred p;\n\t"
            "mbarrier.try_wait.parity.shared.b64 p, [%1], %2, 0x989680;\n\t"
            "selp.b32 %0, 1, 0, p;\n\t}"
            : "=r"(done) : "r"(addr), "r"(parity) : "memory");
    } while (!done);
}

// per-(mesh,batch-tile) group barrier: 8 arrivals per group per tick
__device__ __forceinline__ void grid_barrier(unsigned phase, int m, int bt) {
    __threadfence();
    __syncthreads();
    if (threadIdx.x == 0) {
        asm volatile("red.release.gpu.global.add.u32 [%0], %1;"
                     :: "l"(&g_barp[m][bt]), "r"(1u) : "memory");
        asm volatile("red.release.gpu.global.add.u32 [%0], %1;"
                     :: "l"(&g_barp[(m + 1) & 7][bt]), "r"(1u) : "memory");
        unsigned target = phase * 8u, v;
        do {
            asm volatile("ld.acquire.gpu.global.u32 %0, [%1];"
                         : "=r"(v) : "l"(&g_barp[m][bt]) : "memory");
            if (v < target) __nanosleep(64);
        } while (v < target);
    }
    __syncthreads();
}

// scattered spike write (tick 0 only); kown = gc, prev at 512+gc
__device__ __forceinline__ void write_spike0(int m, int grow, int gc, bool sp) {
    unsigned short h = sp ? 0x3F80 : 0;
    unsigned sw = (((unsigned)grow & 7u) << 4);
    *(unsigned short*)((char*)&g_Abuf[0][m][gc >> 6][grow][0]
                       + (((unsigned)(2 * (gc & 63))) ^ sw)) = h;
    if (gc < NEx) {
        int kp = K_POFF + gc;
        *(unsigned short*)((char*)&g_Abuf[0][(m + 1) & 7][kp >> 6][grow][0]
                           + (((unsigned)(2 * (kp & 63))) ^ sw)) = h;
    }
}

// ---------------- persistent bf16-HMMA reservoir (4-slot ring + B-prefetch) ------------
// smem: slots 4x(A16K+B16K)=128K | v f32 stride 132 (67.6K) | full mbar[4] | scnt[15]
//       spike staging uses slot-2/3 region [65536, 131072) during epilogue
#define SMO_STG  65536
#define SMO_V    131072
#define SMO_MBAR 198656
#define SMO_CNT  198688
#define SM_DYN   198912

__global__ void __launch_bounds__(NTHR, 1)
k_persist(float* __restrict__ dout, float decayI) {
    extern __shared__ __align__(16) char sm[];
    float*    sv   = (float*)(sm + SMO_V);    // stride 132
    unsigned* scnt = (unsigned*)(sm + SMO_CNT);

    const int m   = blockIdx.z;
    const int bt  = blockIdx.y;
    const int bm0 = bt * 128;
    const int bn0 = blockIdx.x * 128;
    const int tid  = threadIdx.x;
    const int lane = tid & 31, warp = tid >> 5;
    const int wm = warp >> 2, wn = warp & 3;      // 4x4 warps, warp tile 32x32

    const int bq      = bn0 >> 7;                 // 0..3
    const int st0     = 2 * bq;                   // own chunk stages
    const int pst0    = 8 + 2 * bq;               // prev chunk stages
    const int prevCnt = (bq == 3) ? 1 : 2;

    unsigned smb   = (unsigned)__cvta_generic_to_shared(sm);
    unsigned mbarb = smb + SMO_MBAR;              // full barriers: +0, +8, +16, +24

    const float4* xp = &g_extp[m][bt][bq][0][tid];   // xp[q*NTHR]

    if (tid == 0) {
        #pragma unroll
        for (int s = 0; s < 4; ++s)
            asm volatile("mbarrier.init.shared.b64 [%0], 2;" :: "r"(mbarb + 8u * s) : "memory");
    }
    __syncthreads();

    // -------- tick 0: v = 0 + ext --------
    for (int i = tid; i < 128 * 128; i += NTHR) {
        int r = i >> 7, c = i & 127;
        float cc   = g_ext[m][bm0 + r][bn0 + c];
        float vnew = __fadd_rn(0.0f, cc);
        float u    = __fadd_rn(vnew, -1.0f);
        bool  sp   = (u >= 0.0f);
        sv[r * 132 + c] = sp ? 0.0f : vnew;
        write_spike0(m, bm0 + r, bn0 + c, sp);
    }

    // spike-count accumulator in registers (thread-owned elements)
    unsigned pack[8];
    #pragma unroll
    for (int q = 0; q < 8; ++q) {
        pack[q] = 0u;
        float4 e4 = __ldg(&xp[q * NTHR]);
        const float* ep = &e4.x;
        #pragma unroll
        for (int f = 0; f < 4; ++f) {
            float vnew = __fadd_rn(0.0f, ep[f]);
            float u    = __fadd_rn(vnew, -1.0f);
            if (u >= 0.0f) pack[q] += (1u << (8 * f));
        }
    }
    if (tid < NS) scnt[tid] = 0u;
    grid_barrier(1, m, bt);

    const int r15   = lane & 15;
    const int kh16  = (lane >> 4) * 16;
    const unsigned swl = (((unsigned)r15 & 7u) << 4);

    unsigned fful = 0;                 // consumer full-parity bits per slot

    for (int t = 1; t < 16; ++t) {
        const int rbuf = (t - 1) & 1, wbuf = t & 1;

        // tick-start: issue A for slots 0,1 (B prefetched last tick) and A+B for 2,3
        if (tid == 0) {
            asm volatile("fence.proxy.async;" ::: "memory");
            #pragma unroll
            for (int s = 0; s < 4; ++s) {
                unsigned mb = mbarb + 8u * s;
                unsigned sbase = smb + (unsigned)s * 32768u;
                mbar_expect(mb, SLOT);
                bulk_ld(sbase, &g_Abuf[rbuf][m][s][bm0][0], SLOT, mb);
                if (t == 1 || s >= 2) {                    // B not prefetched for these
                    mbar_expect(mb, SLOT);
                    bulk_ld(sbase + SLOT, &g_Wbig[m][s][bn0][0], SLOT, mb);
                }
            }
        }

        float c0[2][4][4], c1[2][4][4];
        #pragma unroll
        for (int a = 0; a < 2; ++a)
            #pragma unroll
            for (int b = 0; b < 4; ++b)
                #pragma unroll
                for (int f = 0; f < 4; ++f) { c0[a][b][f] = 0.f; c1[a][b][f] = 0.f; }

        for (int s = 0; s < NS; ++s) {
            int slot = s & 3;
            mbar_wait(mbarb + 8u * slot, (fful >> slot) & 1u);
            fful ^= (1u << slot);

            bool own = (s < OWN_STG);
            unsigned abase = smb + (unsigned)slot * 32768u;
            unsigned bbase = abase + SLOT;
            #pragma unroll
            for (int kk = 0; kk < 4; ++kk) {
                unsigned a[2][4], bfr[2][4];
                unsigned coff = ((unsigned)(kk * 32 + kh16)) ^ swl;
                #pragma unroll
                for (int im = 0; im < 2; ++im)
                    ldm4(a[im], abase + (unsigned)((wm * 32 + im * 16 + r15) * 128) + coff);
                #pragma unroll
                for (int ib = 0; ib < 2; ++ib)
                    ldm4(bfr[ib], bbase + (unsigned)((wn * 32 + ib * 16 + r15) * 128) + coff);
                if (own) {
                    #pragma unroll
                    for (int im = 0; im < 2; ++im)
                        #pragma unroll
                        for (int in = 0; in < 4; ++in) {
                            int ib = in >> 1, sub = in & 1;
                            mma16816(c0[im][in], a[im], bfr[ib][sub], bfr[ib][sub + 2]);
                        }
                } else {
                    #pragma unroll
                    for (int im = 0; im < 2; ++im)
                        #pragma unroll
                        for (int in = 0; in < 4; ++in) {
                            int ib = in >> 1, sub = in & 1;
                            mma16816(c1[im][in], a[im], bfr[ib][sub], bfr[ib][sub + 2]);
                        }
                }
            }
            // distributed producer: LAST warp done with stage s refills SAME slot with s+4
            if (lane == 0) {
                unsigned old = atomicAdd(&scnt[s], 1u);
                if (old == 15u && s + 4 < NS) {
                    int s2 = s + 4;
                    unsigned mb = mbarb + 8u * slot;
                    unsigned sbase = smb + (unsigned)slot * 32768u;
                    mbar_expect(mb, SLOT);
                    bulk_ld(sbase, &g_Abuf[rbuf][m][s2][bm0][0], SLOT, mb);
                    mbar_expect(mb, SLOT);
                    bulk_ld(sbase + SLOT, &g_Wbig[m][s2][bn0][0], SLOT, mb);
                }
            }
        }
        __syncthreads();                 // all warps done; slots 2,3 become staging

        // -------- B-prefetch for next tick's stages 0,1 into slots 0,1 --------
        if (tid == 0 && t < 15) {
            #pragma unroll
            for (int s = 0; s < 2; ++s) {
                unsigned mb = mbarb + 8u * s;
                mbar_expect(mb, SLOT);
                bulk_ld(smb + (unsigned)s * 32768u + SLOT, &g_Wbig[m][s][bn0][0], SLOT, mb);
            }
        }

        // -------- zero only the padded prev chunk (bq==3, chunk idx 2) --------
        if (bq == 3) {
            uint4 z; z.x = z.y = z.z = z.w = 0u;
            uint4* p = (uint4*)(sm + SMO_STG + 2 * 16384);
            for (int i = tid; i < 1024; i += NTHR) p[i] = z;
            __syncthreads();
        }

        // -------- epilogue: LIF (bitwise chain) + staged spike writes --------
        #pragma unroll
        for (int q = 0; q < 8; ++q) {
            float4 e4 = __ldg(&xp[q * NTHR]);
            const float* ep = &e4.x;
            int im = q >> 2, in = q & 3;
            #pragma unroll
            for (int f = 0; f < 4; ++f) {
                int r = wm * 32 + im * 16 + (lane >> 2) + (f >> 1) * 8;
                int c = wn * 32 + in * 8 + (lane & 3) * 2 + (f & 1);
                int gc = bn0 + c;
                int ci = (int)c0[im][in][f];
                int rr = ci & 8191;
                int aEi = (rr < 4096) ? rr : rr - 8192;
                int aIi = (ci - aEi) >> 13;
                float t1   = __fadd_rn(ep[f], c1[im][in][f]);
                float t2   = __fadd_rn(t1, (float)aEi);
                float cur  = __fadd_rn(t2, (float)aIi);
                float vold = sv[r * 132 + c];
                float dec  = (gc < NEx) ? 0.5f : decayI;
                float vnew = __fadd_rn(__fmul_rn(vold, dec), cur);
                float u    = __fadd_rn(vnew, -1.0f);
                bool  sp   = (u >= 0.0f);
                sv[r * 132 + c] = sp ? 0.0f : vnew;
                if (sp) pack[q] += (1u << (8 * f));
                unsigned short h = sp ? 0x3F80 : 0;
                unsigned swr = (((unsigned)r & 7u) << 4);
                unsigned soff = (unsigned)(SMO_STG + (c >> 6) * 16384 + r * 128)
                                + (((unsigned)(2 * (gc & 63))) ^ swr);
                *(unsigned short*)(sm + soff) = h;
                if (gc < NEx)
                    *(unsigned short*)(sm + soff + 32768) = h;
            }
        }
        __syncthreads();

        // -------- bulk stores: staging -> g_Abuf[wbuf] --------
        if (tid == 0) {
            asm volatile("fence.proxy.async.shared::cta;" ::: "memory");
            #pragma unroll
            for (int j = 0; j < 2; ++j)
                bulk_st(&g_Abuf[wbuf][m][st0 + j][bm0][0],
                        smb + (unsigned)(SMO_STG + j * 16384));
            for (int j = 0; j < prevCnt; ++j)
                bulk_st(&g_Abuf[wbuf][(m + 1) & 7][pst0 + j][bm0][0],
                        smb + (unsigned)(SMO_STG + (2 + j) * 16384));
            asm volatile("cp.async.bulk.commit_group;" ::: "memory");
            asm volatile("cp.async.bulk.wait_group 0;" ::: "memory");
        }

        if (t < 15) {
            if (tid < NS) scnt[tid] = 0u;             // reset stage counters
            grid_barrier((unsigned)(t + 1), m, bt);   // syncthreads publishes the reset
        }
    }

    // -------- final: write spike counts from registers --------
    #pragma unroll
    for (int q = 0; q < 8; ++q) {
        int im = q >> 2, in = q & 3;
        #pragma unroll
        for (int f = 0; f < 4; ++f) {
            int r = wm * 32 + im * 16 + (lane >> 2) + (f >> 1) * 8;
            int c = wn * 32 + in * 8 + (lane & 3) * 2 + (f & 1);
            unsigned cnt = (pack[q] >> (8 * f)) & 255u;
            dout[(long long)(bm0 + r) * (MESH * NN) + m * NN + bn0 + c] = (float)cnt;
        }
    }
}

// ---------------- launch ----------------
extern "C" void kernel_launch(void* const* d_in, const int* in_sizes, int n_in,
                              void* d_out, int out_size) {
    const float* x       = (const float*)d_in[0];
    const float* W_in    = (const float*)d_in[1];
    const float* b_in    = (const float*)d_in[2];
    const float* W_inter = (const float*)d_in[3];
    const float* W_EE    = (const float*)d_in[4];
    const float* W_EI    = (const float*)d_in[5];
    const float* W_IE    = (const float*)d_in[6];
    const float* W_II    = (const float*)d_in[7];
    float* out = (float*)d_out;
    const float decayI = (float)(1.0 - 1.0 / 1.5);

    cudaFuncSetAttribute(k_persist, cudaFuncAttributeMaxDynamicSharedMemorySize, SM_DYN);

    // local launch idx 3 == k_persist (ncu capture slot)
    k_init<<<2048, 256>>>(W_in, W_inter, W_EE, W_EI, W_IE, W_II);   // 0
    k_ext<<<dim3(BB / EXT_BT, MESH), 512>>>(x, b_in);               // 1
    k_perm<<<1024, 256>>>();                                        // 2
    dim3 grid(4, 4, 8);                                             // 128 CTAs, 1/SM
    k_persist<<<grid, NTHR, SM_DYN>>>(out, decayI);                 // 3
}